// round 12
// baseline (speedup 1.0000x reference)
#include <cuda_runtime.h>
#include <cstdint>

#define BATCH 64
#define NIN   1024
#define DIN   512
#define NC    32
#define DC    64
#define ZDIM  2048
#define EPSQ  1e-7f
#define BG    16
#define NBG   (BATCH/BG)   // 4
#define WPAD  68
#define WHALF 256
#define LDH   72     // staged u row: 64 halves + pad
#define CLD   136    // staged c row: 128 halves + pad
#define CPD   132    // fp32 transpose-buffer pad

// smem byte offsets for fused kernel (single-buffered)
#define USH 0
#define USL 18432
#define VSH 36864
#define VSL 41472
#define CSH 46080
#define CSL 54784
#define FUSED_SMEM 63488

typedef unsigned long long u64;
typedef unsigned short bfu;

__device__ __align__(16) float g_cspart[4*BATCH*DIN];               // 512 KB
__device__ __align__(16) float g_spart8[(size_t)8*BATCH*NC*DIN];    // 32 MB
__device__ __align__(16) float g_v[BATCH*NC*DIN];                   // 4 MB

// ---------------- helpers ----------------
__device__ __forceinline__ u64 fma2(u64 a, u64 b, u64 c){
  u64 d; asm("fma.rn.f32x2 %0, %1, %2, %3;" : "=l"(d) : "l"(a), "l"(b), "l"(c));
  return d;
}
__device__ __forceinline__ u64 add2(u64 a, u64 b){
  u64 d; asm("add.rn.f32x2 %0, %1, %2;" : "=l"(d) : "l"(a), "l"(b));
  return d;
}
__device__ __forceinline__ float hadd2(u64 v){
  float lo, hi; asm("mov.b64 {%0, %1}, %2;" : "=f"(lo), "=f"(hi) : "l"(v));
  return lo + hi;
}
__device__ __forceinline__ uint32_t smem_u32(const void* p){
  return (uint32_t)__cvta_generic_to_shared(p);
}
__device__ __forceinline__ void bfsplit2(float x0, float x1,
                                         uint32_t& hi, uint32_t& lo){
  asm("cvt.rn.bf16x2.f32 %0, %1, %2;" : "=r"(hi) : "f"(x1), "f"(x0));
  float h0 = __uint_as_float(hi << 16);
  float h1 = __uint_as_float(hi & 0xffff0000u);
  asm("cvt.rn.bf16x2.f32 %0, %1, %2;" : "=r"(lo) : "f"(x1 - h1), "f"(x0 - h0));
}
__device__ __forceinline__ void ldmx4(uint32_t* r, uint32_t addr){
  asm volatile("ldmatrix.sync.aligned.m8n8.x4.shared.b16 {%0,%1,%2,%3}, [%4];"
    : "=r"(r[0]), "=r"(r[1]), "=r"(r[2]), "=r"(r[3]) : "r"(addr));
}
__device__ __forceinline__ void ldmx4t(uint32_t* r, uint32_t addr){
  asm volatile("ldmatrix.sync.aligned.m8n8.x4.trans.shared.b16 {%0,%1,%2,%3}, [%4];"
    : "=r"(r[0]), "=r"(r[1]), "=r"(r[2]), "=r"(r[3]) : "r"(addr));
}
__device__ __forceinline__ void mma16816(float* c, const uint32_t* a,
                                         const uint32_t* b){
  asm volatile("mma.sync.aligned.m16n8k16.row.col.f32.bf16.bf16.f32 "
    "{%0,%1,%2,%3}, {%4,%5,%6,%7}, {%8,%9}, {%0,%1,%2,%3};"
    : "+f"(c[0]), "+f"(c[1]), "+f"(c[2]), "+f"(c[3])
    : "r"(a[0]), "r"(a[1]), "r"(a[2]), "r"(a[3]), "r"(b[0]), "r"(b[1]));
}

// ---------------- colsum ----------------
__global__ void __launch_bounds__(512) colsum_kernel(const float* __restrict__ u){
  int b = blockIdx.x, part = blockIdx.y, k = threadIdx.x;
  const float* up = u + ((size_t)b*NIN + (size_t)part*256)*DIN + k;
  float s = 0.f;
  #pragma unroll 8
  for (int i = 0; i < 256; ++i) s += up[(size_t)i*DIN];
  g_cspart[(part*BATCH + b)*DIN + k] = s;
}

// ---------------- fused routing: logits+softmax (phase1) + accum (phase2)
// single-buffered smem + register prefetch of next chunk
__global__ void __launch_bounds__(256,2) fused_routing(const float* __restrict__ u){
  extern __shared__ __align__(16) char smem[];
  bfu* u_sh = (bfu*)(smem + USH);
  bfu* u_sl = (bfu*)(smem + USL);
  bfu* v_sh = (bfu*)(smem + VSH);
  bfu* v_sl = (bfu*)(smem + VSL);
  bfu* c_sh = (bfu*)(smem + CSH);
  bfu* c_sl = (bfu*)(smem + CSL);
  int b = blockIdx.x, ic = blockIdx.y;
  int t = threadIdx.x, w = t >> 5, l = t & 31;
  const float* ug = u + ((size_t)b*NIN + (size_t)ic*128)*DIN;
  const float* vg = g_v + (size_t)b*NC*DIN;

  int urow[8], uq[8];
  #pragma unroll
  for (int it = 0; it < 8; ++it){
    int idx = it*256 + t; urow[it] = idx >> 4; uq[it] = idx & 15;
  }
  int vn0 = t >> 4, vq0 = t & 15;
  int vn1 = (256 + t) >> 4, vq1 = t & 15;

  // ---- phase 1: logits ----
  uint32_t aoff = ((w*16 + (l & 15))*LDH + (l >> 4)*8)*2;
  uint32_t a_hi = smem_u32(u_sh) + aoff, a_lo = smem_u32(u_sl) + aoff;
  uint32_t boff0 = (((l >> 4)*8 + (l & 7))*LDH + ((l >> 3) & 1)*8)*2;
  uint32_t boff1 = boff0 + 16*LDH*2;
  uint32_t bh0 = smem_u32(v_sh) + boff0, bh1 = smem_u32(v_sh) + boff1;
  uint32_t bl0 = smem_u32(v_sl) + boff0, bl1 = smem_u32(v_sl) + boff1;

  float acc[16];
  #pragma unroll
  for (int i = 0; i < 16; ++i) acc[i] = 0.f;

  float4 pu[8], pv0, pv1;
  #pragma unroll
  for (int it = 0; it < 8; ++it)
    pu[it] = *(const float4*)(ug + (size_t)urow[it]*DIN + uq[it]*4);
  pv0 = *(const float4*)(vg + (size_t)vn0*DIN + vq0*4);
  pv1 = *(const float4*)(vg + (size_t)vn1*DIN + vq1*4);

  for (int kc = 0; kc < 8; ++kc){
    #pragma unroll
    for (int it = 0; it < 8; ++it){
      uint32_t h0, l0, h1, l1;
      bfsplit2(pu[it].x, pu[it].y, h0, l0);
      bfsplit2(pu[it].z, pu[it].w, h1, l1);
      *(uint2*)&u_sh[urow[it]*LDH + uq[it]*4] = make_uint2(h0, h1);
      *(uint2*)&u_sl[urow[it]*LDH + uq[it]*4] = make_uint2(l0, l1);
    }
    {
      uint32_t h0, l0, h1, l1;
      bfsplit2(pv0.x, pv0.y, h0, l0); bfsplit2(pv0.z, pv0.w, h1, l1);
      *(uint2*)&v_sh[vn0*LDH + vq0*4] = make_uint2(h0, h1);
      *(uint2*)&v_sl[vn0*LDH + vq0*4] = make_uint2(l0, l1);
      bfsplit2(pv1.x, pv1.y, h0, l0); bfsplit2(pv1.z, pv1.w, h1, l1);
      *(uint2*)&v_sh[vn1*LDH + vq1*4] = make_uint2(h0, h1);
      *(uint2*)&v_sl[vn1*LDH + vq1*4] = make_uint2(l0, l1);
    }
    if (kc < 7){
      int ko = (kc+1)*64;
      #pragma unroll
      for (int it = 0; it < 8; ++it)
        pu[it] = *(const float4*)(ug + (size_t)urow[it]*DIN + ko + uq[it]*4);
      pv0 = *(const float4*)(vg + (size_t)vn0*DIN + ko + vq0*4);
      pv1 = *(const float4*)(vg + (size_t)vn1*DIN + ko + vq1*4);
    }
    __syncthreads();
    #pragma unroll
    for (int ks = 0; ks < 4; ++ks){
      uint32_t kb = ks*32;
      uint32_t ah[4], al[4], bh[8], bl[8];
      ldmx4(ah, a_hi + kb); ldmx4(al, a_lo + kb);
      ldmx4(bh,   bh0 + kb); ldmx4(bh+4, bh1 + kb);
      ldmx4(bl,   bl0 + kb); ldmx4(bl+4, bl1 + kb);
      #pragma unroll
      for (int nt = 0; nt < 4; ++nt){
        mma16816(acc + nt*4, ah, bh + nt*2);
        mma16816(acc + nt*4, ah, bl + nt*2);
        mma16816(acc + nt*4, al, bh + nt*2);
      }
    }
    __syncthreads();
  }

  // softmax over n, stash c^T fp32 into u_sh alias
  float m0 = -1e30f, m1 = -1e30f;
  #pragma unroll
  for (int nt = 0; nt < 4; ++nt){
    m0 = fmaxf(m0, fmaxf(acc[nt*4], acc[nt*4+1]));
    m1 = fmaxf(m1, fmaxf(acc[nt*4+2], acc[nt*4+3]));
  }
  m0 = fmaxf(m0, __shfl_xor_sync(0xffffffffu, m0, 1));
  m0 = fmaxf(m0, __shfl_xor_sync(0xffffffffu, m0, 2));
  m1 = fmaxf(m1, __shfl_xor_sync(0xffffffffu, m1, 1));
  m1 = fmaxf(m1, __shfl_xor_sync(0xffffffffu, m1, 2));
  float s0 = 0.f, s1 = 0.f;
  #pragma unroll
  for (int nt = 0; nt < 4; ++nt){
    acc[nt*4]   = __expf(acc[nt*4]   - m0); s0 += acc[nt*4];
    acc[nt*4+1] = __expf(acc[nt*4+1] - m0); s0 += acc[nt*4+1];
    acc[nt*4+2] = __expf(acc[nt*4+2] - m1); s1 += acc[nt*4+2];
    acc[nt*4+3] = __expf(acc[nt*4+3] - m1); s1 += acc[nt*4+3];
  }
  s0 += __shfl_xor_sync(0xffffffffu, s0, 1);
  s0 += __shfl_xor_sync(0xffffffffu, s0, 2);
  s1 += __shfl_xor_sync(0xffffffffu, s1, 1);
  s1 += __shfl_xor_sync(0xffffffffu, s1, 2);
  float inv0 = 1.0f/s0, inv1 = 1.0f/s1;

  float* c_ts = (float*)u_sh;   // alias
  int i0 = w*16 + (l >> 2), i1 = i0 + 8;
  #pragma unroll
  for (int nt = 0; nt < 4; ++nt){
    int n = nt*8 + (l & 3)*2;
    c_ts[n*CPD + i0]     = acc[nt*4]*inv0;
    c_ts[(n+1)*CPD + i0] = acc[nt*4+1]*inv0;
    c_ts[n*CPD + i1]     = acc[nt*4+2]*inv1;
    c_ts[(n+1)*CPD + i1] = acc[nt*4+3]*inv1;
  }
  __syncthreads();
  // convert c to bf16 hi/lo [n][i] in c_sh/c_sl
  #pragma unroll
  for (int r = 0; r < 2; ++r){
    int idx = r*256 + t, n = idx >> 4, q = idx & 15;
    const float* src = c_ts + n*CPD + q*8;
    uint32_t h0,l0,h1,l1,h2,l2,h3,l3;
    bfsplit2(src[0], src[1], h0, l0);
    bfsplit2(src[2], src[3], h1, l1);
    bfsplit2(src[4], src[5], h2, l2);
    bfsplit2(src[6], src[7], h3, l3);
    uint4 hv; hv.x=h0; hv.y=h1; hv.z=h2; hv.w=h3;
    uint4 lv; lv.x=l0; lv.y=l1; lv.z=l2; lv.w=l3;
    *(uint4*)&c_sh[n*CLD + q*8] = hv;
    *(uint4*)&c_sl[n*CLD + q*8] = lv;
  }

  // prefetch ch=0 u tile
  #pragma unroll
  for (int it = 0; it < 8; ++it)
    pu[it] = *(const float4*)(ug + (size_t)urow[it]*DIN + uq[it]*4);

  // ---- phase 2: accum s^T partial for this i-tile ----
  int mt = w & 3, nh = w >> 2;
  uint32_t atr_off = (((l & 7) + ((l >> 4) & 1)*8)*LDH + mt*16 + ((l >> 3) & 1)*8)*2;
  uint32_t atr_h = smem_u32(u_sh) + atr_off, atr_l = smem_u32(u_sl) + atr_off;
  uint32_t bco = ((nh*16 + ((l >> 4) & 1)*8 + (l & 7))*CLD + ((l >> 3) & 1)*8)*2;
  uint32_t bc_h = smem_u32(c_sh) + bco, bc_l = smem_u32(c_sl) + bco;
  float* sp = g_spart8 + ((size_t)(ic*BATCH + b)*NC)*DIN;

  for (int ch = 0; ch < 8; ++ch){
    __syncthreads();
    #pragma unroll
    for (int it = 0; it < 8; ++it){
      uint32_t h0, l0, h1, l1;
      bfsplit2(pu[it].x, pu[it].y, h0, l0);
      bfsplit2(pu[it].z, pu[it].w, h1, l1);
      *(uint2*)&u_sh[urow[it]*LDH + uq[it]*4] = make_uint2(h0, h1);
      *(uint2*)&u_sl[urow[it]*LDH + uq[it]*4] = make_uint2(l0, l1);
    }
    if (ch < 7){
      int ko = (ch+1)*64;
      #pragma unroll
      for (int it = 0; it < 8; ++it)
        pu[it] = *(const float4*)(ug + (size_t)urow[it]*DIN + ko + uq[it]*4);
    }
    __syncthreads();
    float sacc[8];
    #pragma unroll
    for (int i = 0; i < 8; ++i) sacc[i] = 0.f;
    #pragma unroll
    for (int is = 0; is < 8; ++is){
      uint32_t ah[4], al[4], bh[4], bl[4];
      ldmx4t(ah, atr_h + is*16*LDH*2);
      ldmx4t(al, atr_l + is*16*LDH*2);
      ldmx4(bh, bc_h + is*32);
      ldmx4(bl, bc_l + is*32);
      #pragma unroll
      for (int nt = 0; nt < 2; ++nt){
        mma16816(sacc + nt*4, ah, bh + nt*2);
        mma16816(sacc + nt*4, ah, bl + nt*2);
        mma16816(sacc + nt*4, al, bh + nt*2);
      }
    }
    int kg = ch*64 + mt*16 + (l >> 2);
    #pragma unroll
    for (int nt = 0; nt < 2; ++nt){
      int n = nh*16 + nt*8 + 2*(l & 3);
      sp[(size_t)n*DIN + kg]       = sacc[nt*4];
      sp[(size_t)(n+1)*DIN + kg]   = sacc[nt*4+1];
      sp[(size_t)n*DIN + kg+8]     = sacc[nt*4+2];
      sp[(size_t)(n+1)*DIN + kg+8] = sacc[nt*4+3];
    }
  }
}

// ---------------- outv: out = squash(W^T s); v = W out  (chunked W, 2 CTA/SM)
#define OUTV_SMEM ((WHALF*WPAD + BG*DIN + BG*DC + BG*2)*4)

__global__ void __launch_bounds__(512,2) outv_kernel(
    const float* __restrict__ W, int mode, int doV, float* __restrict__ outF){
  extern __shared__ __align__(16) float sm[];
  float* W_s  = sm;                    // [256][68]
  float* s_s  = W_s + WHALF*WPAD;      // [16][512]
  float* o_s  = s_s + BG*DIN;          // [16][64]
  float* sq_s = o_s + BG*DC;           // [16][2]
  int n = blockIdx.x, bg = blockIdx.y, t = threadIdx.x;

  // stage s (sum partials)
  for (int m = t; m < BG*DIN/4; m += 512){
    int b = m >> 7, f = (m & 127)*4;
    int gb = bg*BG + b;
    float4 r;
    if (mode == 0){
      float4 a0 = *(const float4*)&g_cspart[(0*BATCH+gb)*DIN + f];
      float4 a1 = *(const float4*)&g_cspart[(1*BATCH+gb)*DIN + f];
      float4 a2 = *(const float4*)&g_cspart[(2*BATCH+gb)*DIN + f];
      float4 a3 = *(const float4*)&g_cspart[(3*BATCH+gb)*DIN + f];
      r.x = a0.x+a1.x+a2.x+a3.x; r.y = a0.y+a1.y+a2.y+a3.y;
      r.z = a0.z+a1.z+a2.z+a3.z; r.w = a0.w+a1.w+a2.w+a3.w;
    } else {
      r.x = r.y = r.z = r.w = 0.f;
      #pragma unroll
      for (int p = 0; p < 8; ++p){
        float4 a = *(const float4*)&g_spart8[((size_t)(p*BATCH+gb)*NC + n)*DIN + f];
        r.x += a.x; r.y += a.y; r.z += a.z; r.w += a.w;
      }
    }
    *(float4*)&s_s[b*DIN + f] = r;
  }

  int d = t & 63, bq = t >> 6, lane = t & 31;
  float acc[2] = {0.f, 0.f};
  // out phase over two W halves
  for (int h = 0; h < 2; ++h){
    __syncthreads();   // protect W_s reuse (h=1) / s_s staging done (h=0)
    for (int m = t; m < WHALF*DC/4; m += 512){
      int k = m >> 4, q = m & 15;
      *(float4*)&W_s[k*WPAD + q*4] =
          *(const float4*)(W + (size_t)(h*WHALF + k)*ZDIM + n*DC + q*4);
    }
    __syncthreads();
    for (int kb = 0; kb < WHALF; kb += 4){
      float w0 = W_s[(kb+0)*WPAD + d], w1 = W_s[(kb+1)*WPAD + d];
      float w2 = W_s[(kb+2)*WPAD + d], w3 = W_s[(kb+3)*WPAD + d];
      #pragma unroll
      for (int j = 0; j < 2; ++j){
        float4 sv = *(const float4*)&s_s[(bq*2+j)*DIN + h*WHALF + kb];
        acc[j] += w0*sv.x + w1*sv.y + w2*sv.z + w3*sv.w;
      }
    }
  }
  int half = d >> 5;
  #pragma unroll
  for (int j = 0; j < 2; ++j){
    float sq = acc[j]*acc[j];
    #pragma unroll
    for (int o = 16; o; o >>= 1) sq += __shfl_xor_sync(0xffffffffu, sq, o);
    if (lane == 0) sq_s[(bq*2+j)*2 + half] = sq;
  }
  __syncthreads();
  #pragma unroll
  for (int j = 0; j < 2; ++j){
    int b = bq*2 + j;
    float inv = rsqrtf(sq_s[b*2] + sq_s[b*2+1] + EPSQ);
    float o = acc[j]*inv;
    o_s[b*DC + d] = o;
    if (outF) outF[((size_t)(bg*BG+b)*NC + n)*DC + d] = o;
  }
  if (!doV) return;

  // v phase: 2 threads per k (d-halves), combined via shfl
  int ks = t >> 1, dh = t & 1;
  for (int h = 0; h < 2; ++h){
    __syncthreads();   // o_s ready (h=0) / previous v reads done (h=1)
    for (int m = t; m < WHALF*DC/4; m += 512){
      int k = m >> 4, q = m & 15;
      *(float4*)&W_s[k*WPAD + q*4] =
          *(const float4*)(W + (size_t)(h*WHALF + k)*ZDIM + n*DC + q*4);
    }
    __syncthreads();
    u64 wr[16];
    #pragma unroll
    for (int q = 0; q < 8; ++q){
      ulonglong2 wv = *(const ulonglong2*)&W_s[ks*WPAD + dh*32 + q*4];
      wr[q*2] = wv.x; wr[q*2+1] = wv.y;
    }
    int kglob = h*WHALF + ks;
    #pragma unroll 2
    for (int b = 0; b < BG; ++b){
      u64 a0 = 0ull, a1 = 0ull;
      const ulonglong2* ob = (const ulonglong2*)&o_s[b*DC + dh*32];
      #pragma unroll
      for (int q = 0; q < 8; ++q){
        ulonglong2 ov = ob[q];
        a0 = fma2(wr[q*2],   ov.x, a0);
        a1 = fma2(wr[q*2+1], ov.y, a1);
      }
      float p = hadd2(add2(a0, a1));
      p += __shfl_xor_sync(0xffffffffu, p, 1);
      if (dh == 0)
        g_v[((size_t)(bg*BG+b)*NC + n)*DIN + kglob] = p;
    }
  }
}

// --------------------------------------------------------------------------
extern "C" void kernel_launch(void* const* d_in, const int* in_sizes, int n_in,
                              void* d_out, int out_size){
  const float* u = (const float*)d_in[0];
  const float* W = (const float*)d_in[1];
  float* out = (float*)d_out;
  (void)in_sizes; (void)n_in; (void)out_size;

  cudaFuncSetAttribute(outv_kernel,
                       cudaFuncAttributeMaxDynamicSharedMemorySize, OUTV_SMEM);
  cudaFuncSetAttribute(fused_routing,
                       cudaFuncAttributeMaxDynamicSharedMemorySize, FUSED_SMEM);

  colsum_kernel<<<dim3(BATCH, 4), 512>>>(u);
  outv_kernel<<<dim3(NC, NBG), 512, OUTV_SMEM>>>(W, 0, 1, nullptr);

  fused_routing<<<dim3(BATCH, 8), 256, FUSED_SMEM>>>(u);
  outv_kernel<<<dim3(NC, NBG), 512, OUTV_SMEM>>>(W, 1, 1, nullptr);

  fused_routing<<<dim3(BATCH, 8), 256, FUSED_SMEM>>>(u);
  outv_kernel<<<dim3(NC, NBG), 512, OUTV_SMEM>>>(W, 1, 0, out);
}

// round 13
// speedup vs baseline: 1.0107x; 1.0107x over previous
#include <cuda_runtime.h>
#include <cstdint>

#define BATCH 64
#define NIN   1024
#define DIN   512
#define NC    32
#define DC    64
#define ZDIM  2048
#define EPSQ  1e-7f
#define BG    16
#define NBG   (BATCH/BG)   // 4
#define WPAD  68
#define LDH   72     // staged u row: 64 halves + pad
#define CLD   136    // staged c row: 128 halves + pad
#define CPD   132    // fp32 transpose-buffer pad

// smem byte offsets for fused kernel (single-buffered)
#define USH 0
#define USL 18432
#define VSH 36864
#define VSL 41472
#define CSH 46080
#define CSL 54784
#define FUSED_SMEM 63488

typedef unsigned long long u64;
typedef unsigned short bfu;

__device__ __align__(16) float g_cspart[4*BATCH*DIN];               // 512 KB
__device__ __align__(16) float g_spart8[(size_t)8*BATCH*NC*DIN];    // 32 MB
__device__ __align__(16) float g_v[BATCH*NC*DIN];                   // 4 MB

// ---------------- helpers ----------------
__device__ __forceinline__ u64 fma2(u64 a, u64 b, u64 c){
  u64 d; asm("fma.rn.f32x2 %0, %1, %2, %3;" : "=l"(d) : "l"(a), "l"(b), "l"(c));
  return d;
}
__device__ __forceinline__ u64 add2(u64 a, u64 b){
  u64 d; asm("add.rn.f32x2 %0, %1, %2;" : "=l"(d) : "l"(a), "l"(b));
  return d;
}
__device__ __forceinline__ float hadd2(u64 v){
  float lo, hi; asm("mov.b64 {%0, %1}, %2;" : "=f"(lo), "=f"(hi) : "l"(v));
  return lo + hi;
}
__device__ __forceinline__ uint32_t smem_u32(const void* p){
  return (uint32_t)__cvta_generic_to_shared(p);
}
__device__ __forceinline__ void bfsplit2(float x0, float x1,
                                         uint32_t& hi, uint32_t& lo){
  asm("cvt.rn.bf16x2.f32 %0, %1, %2;" : "=r"(hi) : "f"(x1), "f"(x0));
  float h0 = __uint_as_float(hi << 16);
  float h1 = __uint_as_float(hi & 0xffff0000u);
  asm("cvt.rn.bf16x2.f32 %0, %1, %2;" : "=r"(lo) : "f"(x1 - h1), "f"(x0 - h0));
}
__device__ __forceinline__ void ldmx4(uint32_t* r, uint32_t addr){
  asm volatile("ldmatrix.sync.aligned.m8n8.x4.shared.b16 {%0,%1,%2,%3}, [%4];"
    : "=r"(r[0]), "=r"(r[1]), "=r"(r[2]), "=r"(r[3]) : "r"(addr));
}
__device__ __forceinline__ void ldmx4t(uint32_t* r, uint32_t addr){
  asm volatile("ldmatrix.sync.aligned.m8n8.x4.trans.shared.b16 {%0,%1,%2,%3}, [%4];"
    : "=r"(r[0]), "=r"(r[1]), "=r"(r[2]), "=r"(r[3]) : "r"(addr));
}
__device__ __forceinline__ void mma16816(float* c, const uint32_t* a,
                                         const uint32_t* b){
  asm volatile("mma.sync.aligned.m16n8k16.row.col.f32.bf16.bf16.f32 "
    "{%0,%1,%2,%3}, {%4,%5,%6,%7}, {%8,%9}, {%0,%1,%2,%3};"
    : "+f"(c[0]), "+f"(c[1]), "+f"(c[2]), "+f"(c[3])
    : "r"(a[0]), "r"(a[1]), "r"(a[2]), "r"(a[3]), "r"(b[0]), "r"(b[1]));
}

// ---------------- colsum ----------------
__global__ void __launch_bounds__(512) colsum_kernel(const float* __restrict__ u){
  int b = blockIdx.x, part = blockIdx.y, k = threadIdx.x;
  const float* up = u + ((size_t)b*NIN + (size_t)part*256)*DIN + k;
  float s = 0.f;
  #pragma unroll 8
  for (int i = 0; i < 256; ++i) s += up[(size_t)i*DIN];
  g_cspart[(part*BATCH + b)*DIN + k] = s;
}

// ---------------- fused routing: logits+softmax (phase1) + accum (phase2)
// single-buffered smem + register prefetch of next chunk
__global__ void __launch_bounds__(256,2) fused_routing(const float* __restrict__ u){
  extern __shared__ __align__(16) char smem[];
  bfu* u_sh = (bfu*)(smem + USH);
  bfu* u_sl = (bfu*)(smem + USL);
  bfu* v_sh = (bfu*)(smem + VSH);
  bfu* v_sl = (bfu*)(smem + VSL);
  bfu* c_sh = (bfu*)(smem + CSH);
  bfu* c_sl = (bfu*)(smem + CSL);
  int b = blockIdx.x, ic = blockIdx.y;
  int t = threadIdx.x, w = t >> 5, l = t & 31;
  const float* ug = u + ((size_t)b*NIN + (size_t)ic*128)*DIN;
  const float* vg = g_v + (size_t)b*NC*DIN;

  int urow[8], uq[8];
  #pragma unroll
  for (int it = 0; it < 8; ++it){
    int idx = it*256 + t; urow[it] = idx >> 4; uq[it] = idx & 15;
  }
  int vn0 = t >> 4, vq0 = t & 15;
  int vn1 = (256 + t) >> 4, vq1 = t & 15;

  // ---- phase 1: logits ----
  uint32_t aoff = ((w*16 + (l & 15))*LDH + (l >> 4)*8)*2;
  uint32_t a_hi = smem_u32(u_sh) + aoff, a_lo = smem_u32(u_sl) + aoff;
  uint32_t boff0 = (((l >> 4)*8 + (l & 7))*LDH + ((l >> 3) & 1)*8)*2;
  uint32_t boff1 = boff0 + 16*LDH*2;
  uint32_t bh0 = smem_u32(v_sh) + boff0, bh1 = smem_u32(v_sh) + boff1;
  uint32_t bl0 = smem_u32(v_sl) + boff0, bl1 = smem_u32(v_sl) + boff1;

  float acc[16];
  #pragma unroll
  for (int i = 0; i < 16; ++i) acc[i] = 0.f;

  float4 pu[8], pv0, pv1;
  #pragma unroll
  for (int it = 0; it < 8; ++it)
    pu[it] = *(const float4*)(ug + (size_t)urow[it]*DIN + uq[it]*4);
  pv0 = *(const float4*)(vg + (size_t)vn0*DIN + vq0*4);
  pv1 = *(const float4*)(vg + (size_t)vn1*DIN + vq1*4);

  for (int kc = 0; kc < 8; ++kc){
    #pragma unroll
    for (int it = 0; it < 8; ++it){
      uint32_t h0, l0, h1, l1;
      bfsplit2(pu[it].x, pu[it].y, h0, l0);
      bfsplit2(pu[it].z, pu[it].w, h1, l1);
      *(uint2*)&u_sh[urow[it]*LDH + uq[it]*4] = make_uint2(h0, h1);
      *(uint2*)&u_sl[urow[it]*LDH + uq[it]*4] = make_uint2(l0, l1);
    }
    {
      uint32_t h0, l0, h1, l1;
      bfsplit2(pv0.x, pv0.y, h0, l0); bfsplit2(pv0.z, pv0.w, h1, l1);
      *(uint2*)&v_sh[vn0*LDH + vq0*4] = make_uint2(h0, h1);
      *(uint2*)&v_sl[vn0*LDH + vq0*4] = make_uint2(l0, l1);
      bfsplit2(pv1.x, pv1.y, h0, l0); bfsplit2(pv1.z, pv1.w, h1, l1);
      *(uint2*)&v_sh[vn1*LDH + vq1*4] = make_uint2(h0, h1);
      *(uint2*)&v_sl[vn1*LDH + vq1*4] = make_uint2(l0, l1);
    }
    if (kc < 7){
      int ko = (kc+1)*64;
      #pragma unroll
      for (int it = 0; it < 8; ++it)
        pu[it] = *(const float4*)(ug + (size_t)urow[it]*DIN + ko + uq[it]*4);
      pv0 = *(const float4*)(vg + (size_t)vn0*DIN + ko + vq0*4);
      pv1 = *(const float4*)(vg + (size_t)vn1*DIN + ko + vq1*4);
    }
    __syncthreads();
    #pragma unroll
    for (int ks = 0; ks < 4; ++ks){
      uint32_t kb = ks*32;
      uint32_t ah[4], al[4], bh[8], bl[8];
      ldmx4(ah, a_hi + kb); ldmx4(al, a_lo + kb);
      ldmx4(bh,   bh0 + kb); ldmx4(bh+4, bh1 + kb);
      ldmx4(bl,   bl0 + kb); ldmx4(bl+4, bl1 + kb);
      #pragma unroll
      for (int nt = 0; nt < 4; ++nt){
        mma16816(acc + nt*4, ah, bh + nt*2);
        mma16816(acc + nt*4, ah, bl + nt*2);
        mma16816(acc + nt*4, al, bh + nt*2);
      }
    }
    __syncthreads();
  }

  // softmax over n, stash c^T fp32 into u_sh alias
  float m0 = -1e30f, m1 = -1e30f;
  #pragma unroll
  for (int nt = 0; nt < 4; ++nt){
    m0 = fmaxf(m0, fmaxf(acc[nt*4], acc[nt*4+1]));
    m1 = fmaxf(m1, fmaxf(acc[nt*4+2], acc[nt*4+3]));
  }
  m0 = fmaxf(m0, __shfl_xor_sync(0xffffffffu, m0, 1));
  m0 = fmaxf(m0, __shfl_xor_sync(0xffffffffu, m0, 2));
  m1 = fmaxf(m1, __shfl_xor_sync(0xffffffffu, m1, 1));
  m1 = fmaxf(m1, __shfl_xor_sync(0xffffffffu, m1, 2));
  float s0 = 0.f, s1 = 0.f;
  #pragma unroll
  for (int nt = 0; nt < 4; ++nt){
    acc[nt*4]   = __expf(acc[nt*4]   - m0); s0 += acc[nt*4];
    acc[nt*4+1] = __expf(acc[nt*4+1] - m0); s0 += acc[nt*4+1];
    acc[nt*4+2] = __expf(acc[nt*4+2] - m1); s1 += acc[nt*4+2];
    acc[nt*4+3] = __expf(acc[nt*4+3] - m1); s1 += acc[nt*4+3];
  }
  s0 += __shfl_xor_sync(0xffffffffu, s0, 1);
  s0 += __shfl_xor_sync(0xffffffffu, s0, 2);
  s1 += __shfl_xor_sync(0xffffffffu, s1, 1);
  s1 += __shfl_xor_sync(0xffffffffu, s1, 2);
  float inv0 = 1.0f/s0, inv1 = 1.0f/s1;

  float* c_ts = (float*)u_sh;   // alias
  int i0 = w*16 + (l >> 2), i1 = i0 + 8;
  #pragma unroll
  for (int nt = 0; nt < 4; ++nt){
    int n = nt*8 + (l & 3)*2;
    c_ts[n*CPD + i0]     = acc[nt*4]*inv0;
    c_ts[(n+1)*CPD + i0] = acc[nt*4+1]*inv0;
    c_ts[n*CPD + i1]     = acc[nt*4+2]*inv1;
    c_ts[(n+1)*CPD + i1] = acc[nt*4+3]*inv1;
  }
  __syncthreads();
  // convert c to bf16 hi/lo [n][i] in c_sh/c_sl
  #pragma unroll
  for (int r = 0; r < 2; ++r){
    int idx = r*256 + t, n = idx >> 4, q = idx & 15;
    const float* src = c_ts + n*CPD + q*8;
    uint32_t h0,l0,h1,l1,h2,l2,h3,l3;
    bfsplit2(src[0], src[1], h0, l0);
    bfsplit2(src[2], src[3], h1, l1);
    bfsplit2(src[4], src[5], h2, l2);
    bfsplit2(src[6], src[7], h3, l3);
    uint4 hv; hv.x=h0; hv.y=h1; hv.z=h2; hv.w=h3;
    uint4 lv; lv.x=l0; lv.y=l1; lv.z=l2; lv.w=l3;
    *(uint4*)&c_sh[n*CLD + q*8] = hv;
    *(uint4*)&c_sl[n*CLD + q*8] = lv;
  }

  // prefetch ch=0 u tile
  #pragma unroll
  for (int it = 0; it < 8; ++it)
    pu[it] = *(const float4*)(ug + (size_t)urow[it]*DIN + uq[it]*4);

  // ---- phase 2: accum s^T partial for this i-tile ----
  int mt = w & 3, nh = w >> 2;
  uint32_t atr_off = (((l & 7) + ((l >> 4) & 1)*8)*LDH + mt*16 + ((l >> 3) & 1)*8)*2;
  uint32_t atr_h = smem_u32(u_sh) + atr_off, atr_l = smem_u32(u_sl) + atr_off;
  uint32_t bco = ((nh*16 + ((l >> 4) & 1)*8 + (l & 7))*CLD + ((l >> 3) & 1)*8)*2;
  uint32_t bc_h = smem_u32(c_sh) + bco, bc_l = smem_u32(c_sl) + bco;
  float* sp = g_spart8 + ((size_t)(ic*BATCH + b)*NC)*DIN;

  for (int ch = 0; ch < 8; ++ch){
    __syncthreads();
    #pragma unroll
    for (int it = 0; it < 8; ++it){
      uint32_t h0, l0, h1, l1;
      bfsplit2(pu[it].x, pu[it].y, h0, l0);
      bfsplit2(pu[it].z, pu[it].w, h1, l1);
      *(uint2*)&u_sh[urow[it]*LDH + uq[it]*4] = make_uint2(h0, h1);
      *(uint2*)&u_sl[urow[it]*LDH + uq[it]*4] = make_uint2(l0, l1);
    }
    if (ch < 7){
      int ko = (ch+1)*64;
      #pragma unroll
      for (int it = 0; it < 8; ++it)
        pu[it] = *(const float4*)(ug + (size_t)urow[it]*DIN + ko + uq[it]*4);
    }
    __syncthreads();
    float sacc[8];
    #pragma unroll
    for (int i = 0; i < 8; ++i) sacc[i] = 0.f;
    #pragma unroll
    for (int is = 0; is < 8; ++is){
      uint32_t ah[4], al[4], bh[4], bl[4];
      ldmx4t(ah, atr_h + is*16*LDH*2);
      ldmx4t(al, atr_l + is*16*LDH*2);
      ldmx4(bh, bc_h + is*32);
      ldmx4(bl, bc_l + is*32);
      #pragma unroll
      for (int nt = 0; nt < 2; ++nt){
        mma16816(sacc + nt*4, ah, bh + nt*2);
        mma16816(sacc + nt*4, ah, bl + nt*2);
        mma16816(sacc + nt*4, al, bh + nt*2);
      }
    }
    int kg = ch*64 + mt*16 + (l >> 2);
    #pragma unroll
    for (int nt = 0; nt < 2; ++nt){
      int n = nh*16 + nt*8 + 2*(l & 3);
      sp[(size_t)n*DIN + kg]       = sacc[nt*4];
      sp[(size_t)(n+1)*DIN + kg]   = sacc[nt*4+1];
      sp[(size_t)n*DIN + kg+8]     = sacc[nt*4+2];
      sp[(size_t)(n+1)*DIN + kg+8] = sacc[nt*4+3];
    }
  }
}

// ---------------- outv: out = squash(W^T s); v = W out ----------------
#define OUTV_SMEM ((DIN*WPAD + BG*DIN + BG*DC + BG*2)*4)

__global__ void __launch_bounds__(512,1) outv_kernel(
    const float* __restrict__ W, int mode, int doV, float* __restrict__ outF){
  extern __shared__ __align__(16) float sm[];
  float* W_s  = sm;
  float* s_s  = W_s + DIN*WPAD;
  float* o_s  = s_s + BG*DIN;
  float* sq_s = o_s + BG*DC;
  int n = blockIdx.x, bg = blockIdx.y, t = threadIdx.x;

  for (int m = t; m < DIN*DC/4; m += 512){
    int k = m >> 4, q = m & 15;
    *(float4*)&W_s[k*WPAD + q*4] = *(const float4*)(W + (size_t)k*ZDIM + n*DC + q*4);
  }
  for (int m = t; m < BG*DIN/4; m += 512){
    int b = m >> 7, f = (m & 127)*4;
    int gb = bg*BG + b;
    float4 r;
    if (mode == 0){
      float4 a0 = *(const float4*)&g_cspart[(0*BATCH+gb)*DIN + f];
      float4 a1 = *(const float4*)&g_cspart[(1*BATCH+gb)*DIN + f];
      float4 a2 = *(const float4*)&g_cspart[(2*BATCH+gb)*DIN + f];
      float4 a3 = *(const float4*)&g_cspart[(3*BATCH+gb)*DIN + f];
      r.x = a0.x+a1.x+a2.x+a3.x; r.y = a0.y+a1.y+a2.y+a3.y;
      r.z = a0.z+a1.z+a2.z+a3.z; r.w = a0.w+a1.w+a2.w+a3.w;
    } else {
      r.x = r.y = r.z = r.w = 0.f;
      #pragma unroll
      for (int p = 0; p < 8; ++p){
        float4 a = *(const float4*)&g_spart8[((size_t)(p*BATCH+gb)*NC + n)*DIN + f];
        r.x += a.x; r.y += a.y; r.z += a.z; r.w += a.w;
      }
    }
    *(float4*)&s_s[b*DIN + f] = r;
  }
  __syncthreads();

  int d = t & 63, bq = t >> 6, lane = t & 31;
  // out phase: kb blocks of 8, two independent accumulator pairs (ILP)
  float accA[2] = {0.f, 0.f}, accB[2] = {0.f, 0.f};
  for (int kb = 0; kb < DIN; kb += 8){
    float w0 = W_s[(kb+0)*WPAD + d], w1 = W_s[(kb+1)*WPAD + d];
    float w2 = W_s[(kb+2)*WPAD + d], w3 = W_s[(kb+3)*WPAD + d];
    float w4 = W_s[(kb+4)*WPAD + d], w5 = W_s[(kb+5)*WPAD + d];
    float w6 = W_s[(kb+6)*WPAD + d], w7 = W_s[(kb+7)*WPAD + d];
    #pragma unroll
    for (int j = 0; j < 2; ++j){
      float4 sa = *(const float4*)&s_s[(bq*2+j)*DIN + kb];
      float4 sbv = *(const float4*)&s_s[(bq*2+j)*DIN + kb + 4];
      accA[j] += w0*sa.x + w1*sa.y + w2*sa.z + w3*sa.w;
      accB[j] += w4*sbv.x + w5*sbv.y + w6*sbv.z + w7*sbv.w;
    }
  }
  float acc[2] = {accA[0] + accB[0], accA[1] + accB[1]};
  int half = d >> 5;
  #pragma unroll
  for (int j = 0; j < 2; ++j){
    float sq = acc[j]*acc[j];
    #pragma unroll
    for (int o = 16; o; o >>= 1) sq += __shfl_xor_sync(0xffffffffu, sq, o);
    if (lane == 0) sq_s[(bq*2+j)*2 + half] = sq;
  }
  __syncthreads();
  #pragma unroll
  for (int j = 0; j < 2; ++j){
    int b = bq*2 + j;
    float inv = rsqrtf(sq_s[b*2] + sq_s[b*2+1] + EPSQ);
    float o = acc[j]*inv;
    o_s[b*DC + d] = o;
    if (outF) outF[((size_t)(bg*BG+b)*NC + n)*DC + d] = o;
  }
  if (!doV) return;
  __syncthreads();

  {
    int k = t;
    u64 wr[32];
    #pragma unroll
    for (int q = 0; q < 16; ++q){
      ulonglong2 wv = *(const ulonglong2*)&W_s[k*WPAD + q*4];
      wr[q*2] = wv.x; wr[q*2+1] = wv.y;
    }
    #pragma unroll 2
    for (int b = 0; b < BG; ++b){
      u64 a0 = 0ull, a1 = 0ull;
      const ulonglong2* ob = (const ulonglong2*)&o_s[b*DC];
      #pragma unroll
      for (int q = 0; q < 16; ++q){
        ulonglong2 ov = ob[q];
        a0 = fma2(wr[q*2], ov.x, a0);
        a1 = fma2(wr[q*2+1], ov.y, a1);
      }
      g_v[((size_t)(bg*BG+b)*NC + n)*DIN + k] = hadd2(add2(a0, a1));
    }
  }
}

// --------------------------------------------------------------------------
extern "C" void kernel_launch(void* const* d_in, const int* in_sizes, int n_in,
                              void* d_out, int out_size){
  const float* u = (const float*)d_in[0];
  const float* W = (const float*)d_in[1];
  float* out = (float*)d_out;
  (void)in_sizes; (void)n_in; (void)out_size;

  cudaFuncSetAttribute(outv_kernel,
                       cudaFuncAttributeMaxDynamicSharedMemorySize, OUTV_SMEM);
  cudaFuncSetAttribute(fused_routing,
                       cudaFuncAttributeMaxDynamicSharedMemorySize, FUSED_SMEM);

  colsum_kernel<<<dim3(BATCH, 4), 512>>>(u);
  outv_kernel<<<dim3(NC, NBG), 512, OUTV_SMEM>>>(W, 0, 1, nullptr);

  fused_routing<<<dim3(BATCH, 8), 256, FUSED_SMEM>>>(u);
  outv_kernel<<<dim3(NC, NBG), 512, OUTV_SMEM>>>(W, 1, 1, nullptr);

  fused_routing<<<dim3(BATCH, 8), 256, FUSED_SMEM>>>(u);
  outv_kernel<<<dim3(NC, NBG), 512, OUTV_SMEM>>>(W, 1, 0, out);
}

// round 14
// speedup vs baseline: 1.0245x; 1.0136x over previous
#include <cuda_runtime.h>
#include <cstdint>

#define BATCH 64
#define NIN   1024
#define DIN   512
#define NC    32
#define DC    64
#define ZDIM  2048
#define EPSQ  1e-7f
#define BG    16
#define NBG   (BATCH/BG)   // 4
#define WPAD  68
#define LDH   72     // staged u row: 64 halves + pad
#define CLD2  264    // staged c row: 256 halves + pad
#define CPD   132    // fp32 transpose-buffer pad

// smem byte offsets for fused kernel (single-buffered u/v, 256-i c)
#define USH 0
#define USL 18432
#define VSH 36864
#define VSL 41472
#define CSH 46080
#define CSL 62976
#define FUSED_SMEM 79872

typedef unsigned long long u64;
typedef unsigned short bfu;

__device__ __align__(16) float g_cspart[4*BATCH*DIN];               // 512 KB
__device__ __align__(16) float g_spart4[(size_t)4*BATCH*NC*DIN];    // 16 MB
__device__ __align__(16) float g_v[BATCH*NC*DIN];                   // 4 MB

// ---------------- helpers ----------------
__device__ __forceinline__ u64 fma2(u64 a, u64 b, u64 c){
  u64 d; asm("fma.rn.f32x2 %0, %1, %2, %3;" : "=l"(d) : "l"(a), "l"(b), "l"(c));
  return d;
}
__device__ __forceinline__ u64 add2(u64 a, u64 b){
  u64 d; asm("add.rn.f32x2 %0, %1, %2;" : "=l"(d) : "l"(a), "l"(b));
  return d;
}
__device__ __forceinline__ float hadd2(u64 v){
  float lo, hi; asm("mov.b64 {%0, %1}, %2;" : "=f"(lo), "=f"(hi) : "l"(v));
  return lo + hi;
}
__device__ __forceinline__ uint32_t smem_u32(const void* p){
  return (uint32_t)__cvta_generic_to_shared(p);
}
__device__ __forceinline__ void bfsplit2(float x0, float x1,
                                         uint32_t& hi, uint32_t& lo){
  asm("cvt.rn.bf16x2.f32 %0, %1, %2;" : "=r"(hi) : "f"(x1), "f"(x0));
  float h0 = __uint_as_float(hi << 16);
  float h1 = __uint_as_float(hi & 0xffff0000u);
  asm("cvt.rn.bf16x2.f32 %0, %1, %2;" : "=r"(lo) : "f"(x1 - h1), "f"(x0 - h0));
}
__device__ __forceinline__ void ldmx4(uint32_t* r, uint32_t addr){
  asm volatile("ldmatrix.sync.aligned.m8n8.x4.shared.b16 {%0,%1,%2,%3}, [%4];"
    : "=r"(r[0]), "=r"(r[1]), "=r"(r[2]), "=r"(r[3]) : "r"(addr));
}
__device__ __forceinline__ void ldmx4t(uint32_t* r, uint32_t addr){
  asm volatile("ldmatrix.sync.aligned.m8n8.x4.trans.shared.b16 {%0,%1,%2,%3}, [%4];"
    : "=r"(r[0]), "=r"(r[1]), "=r"(r[2]), "=r"(r[3]) : "r"(addr));
}
__device__ __forceinline__ void mma16816(float* c, const uint32_t* a,
                                         const uint32_t* b){
  asm volatile("mma.sync.aligned.m16n8k16.row.col.f32.bf16.bf16.f32 "
    "{%0,%1,%2,%3}, {%4,%5,%6,%7}, {%8,%9}, {%0,%1,%2,%3};"
    : "+f"(c[0]), "+f"(c[1]), "+f"(c[2]), "+f"(c[3])
    : "r"(a[0]), "r"(a[1]), "r"(a[2]), "r"(a[3]), "r"(b[0]), "r"(b[1]));
}

// ---------------- colsum ----------------
__global__ void __launch_bounds__(512) colsum_kernel(const float* __restrict__ u){
  int b = blockIdx.x, part = blockIdx.y, k = threadIdx.x;
  const float* up = u + ((size_t)b*NIN + (size_t)part*256)*DIN + k;
  float s = 0.f;
  #pragma unroll 8
  for (int i = 0; i < 256; ++i) s += up[(size_t)i*DIN];
  g_cspart[(part*BATCH + b)*DIN + k] = s;
}

// ---------------- fused routing: 256-i tiles; logits+softmax x2 + accum ----
__global__ void __launch_bounds__(256,2) fused_routing(const float* __restrict__ u){
  extern __shared__ __align__(16) char smem[];
  bfu* u_sh = (bfu*)(smem + USH);
  bfu* u_sl = (bfu*)(smem + USL);
  bfu* v_sh = (bfu*)(smem + VSH);
  bfu* v_sl = (bfu*)(smem + VSL);
  bfu* c_sh = (bfu*)(smem + CSH);
  bfu* c_sl = (bfu*)(smem + CSL);
  int b = blockIdx.x, ic = blockIdx.y;           // ic in 0..3 (256 i each)
  int t = threadIdx.x, w = t >> 5, l = t & 31;
  const float* ub_base = u + ((size_t)b*NIN + (size_t)ic*256)*DIN;
  const float* vg = g_v + (size_t)b*NC*DIN;

  int urow[8], uq[8];
  #pragma unroll
  for (int it = 0; it < 8; ++it){
    int idx = it*256 + t; urow[it] = idx >> 4; uq[it] = idx & 15;
  }
  int vn0 = t >> 4, vq0 = t & 15;
  int vn1 = (256 + t) >> 4, vq1 = t & 15;

  uint32_t aoff = ((w*16 + (l & 15))*LDH + (l >> 4)*8)*2;
  uint32_t a_hi = smem_u32(u_sh) + aoff, a_lo = smem_u32(u_sl) + aoff;
  uint32_t boff0 = (((l >> 4)*8 + (l & 7))*LDH + ((l >> 3) & 1)*8)*2;
  uint32_t boff1 = boff0 + 16*LDH*2;
  uint32_t bh0 = smem_u32(v_sh) + boff0, bh1 = smem_u32(v_sh) + boff1;
  uint32_t bl0 = smem_u32(v_sl) + boff0, bl1 = smem_u32(v_sl) + boff1;

  float4 pu[8], pv0, pv1;

  // ---- phase 1: logits + softmax + c-convert, two 128-i subtiles ----
  for (int sub = 0; sub < 2; ++sub){
    const float* ug = ub_base + (size_t)sub*128*DIN;
    float acc[16];
    #pragma unroll
    for (int i = 0; i < 16; ++i) acc[i] = 0.f;

    #pragma unroll
    for (int it = 0; it < 8; ++it)
      pu[it] = *(const float4*)(ug + (size_t)urow[it]*DIN + uq[it]*4);
    pv0 = *(const float4*)(vg + (size_t)vn0*DIN + vq0*4);
    pv1 = *(const float4*)(vg + (size_t)vn1*DIN + vq1*4);

    for (int kc = 0; kc < 8; ++kc){
      #pragma unroll
      for (int it = 0; it < 8; ++it){
        uint32_t h0, l0, h1, l1;
        bfsplit2(pu[it].x, pu[it].y, h0, l0);
        bfsplit2(pu[it].z, pu[it].w, h1, l1);
        *(uint2*)&u_sh[urow[it]*LDH + uq[it]*4] = make_uint2(h0, h1);
        *(uint2*)&u_sl[urow[it]*LDH + uq[it]*4] = make_uint2(l0, l1);
      }
      {
        uint32_t h0, l0, h1, l1;
        bfsplit2(pv0.x, pv0.y, h0, l0); bfsplit2(pv0.z, pv0.w, h1, l1);
        *(uint2*)&v_sh[vn0*LDH + vq0*4] = make_uint2(h0, h1);
        *(uint2*)&v_sl[vn0*LDH + vq0*4] = make_uint2(l0, l1);
        bfsplit2(pv1.x, pv1.y, h0, l0); bfsplit2(pv1.z, pv1.w, h1, l1);
        *(uint2*)&v_sh[vn1*LDH + vq1*4] = make_uint2(h0, h1);
        *(uint2*)&v_sl[vn1*LDH + vq1*4] = make_uint2(l0, l1);
      }
      if (kc < 7){
        int ko = (kc+1)*64;
        #pragma unroll
        for (int it = 0; it < 8; ++it)
          pu[it] = *(const float4*)(ug + (size_t)urow[it]*DIN + ko + uq[it]*4);
        pv0 = *(const float4*)(vg + (size_t)vn0*DIN + ko + vq0*4);
        pv1 = *(const float4*)(vg + (size_t)vn1*DIN + ko + vq1*4);
      }
      __syncthreads();
      #pragma unroll
      for (int ks = 0; ks < 4; ++ks){
        uint32_t kb = ks*32;
        uint32_t ah[4], al[4], bh[8], bl[8];
        ldmx4(ah, a_hi + kb); ldmx4(al, a_lo + kb);
        ldmx4(bh,   bh0 + kb); ldmx4(bh+4, bh1 + kb);
        ldmx4(bl,   bl0 + kb); ldmx4(bl+4, bl1 + kb);
        #pragma unroll
        for (int nt = 0; nt < 4; ++nt){
          mma16816(acc + nt*4, ah, bh + nt*2);
          mma16816(acc + nt*4, ah, bl + nt*2);
          mma16816(acc + nt*4, al, bh + nt*2);
        }
      }
      __syncthreads();
    }

    // softmax over n, stash c^T fp32 into u_sh alias
    float m0 = -1e30f, m1 = -1e30f;
    #pragma unroll
    for (int nt = 0; nt < 4; ++nt){
      m0 = fmaxf(m0, fmaxf(acc[nt*4], acc[nt*4+1]));
      m1 = fmaxf(m1, fmaxf(acc[nt*4+2], acc[nt*4+3]));
    }
    m0 = fmaxf(m0, __shfl_xor_sync(0xffffffffu, m0, 1));
    m0 = fmaxf(m0, __shfl_xor_sync(0xffffffffu, m0, 2));
    m1 = fmaxf(m1, __shfl_xor_sync(0xffffffffu, m1, 1));
    m1 = fmaxf(m1, __shfl_xor_sync(0xffffffffu, m1, 2));
    float s0 = 0.f, s1 = 0.f;
    #pragma unroll
    for (int nt = 0; nt < 4; ++nt){
      acc[nt*4]   = __expf(acc[nt*4]   - m0); s0 += acc[nt*4];
      acc[nt*4+1] = __expf(acc[nt*4+1] - m0); s0 += acc[nt*4+1];
      acc[nt*4+2] = __expf(acc[nt*4+2] - m1); s1 += acc[nt*4+2];
      acc[nt*4+3] = __expf(acc[nt*4+3] - m1); s1 += acc[nt*4+3];
    }
    s0 += __shfl_xor_sync(0xffffffffu, s0, 1);
    s0 += __shfl_xor_sync(0xffffffffu, s0, 2);
    s1 += __shfl_xor_sync(0xffffffffu, s1, 1);
    s1 += __shfl_xor_sync(0xffffffffu, s1, 2);
    float inv0 = 1.0f/s0, inv1 = 1.0f/s1;

    float* c_ts = (float*)u_sh;   // alias
    int i0 = w*16 + (l >> 2), i1 = i0 + 8;
    #pragma unroll
    for (int nt = 0; nt < 4; ++nt){
      int n = nt*8 + (l & 3)*2;
      c_ts[n*CPD + i0]     = acc[nt*4]*inv0;
      c_ts[(n+1)*CPD + i0] = acc[nt*4+1]*inv0;
      c_ts[n*CPD + i1]     = acc[nt*4+2]*inv1;
      c_ts[(n+1)*CPD + i1] = acc[nt*4+3]*inv1;
    }
    __syncthreads();
    // convert c subtile to bf16 hi/lo at column offset sub*128
    #pragma unroll
    for (int r = 0; r < 2; ++r){
      int idx = r*256 + t, n = idx >> 4, q = idx & 15;
      const float* src = c_ts + n*CPD + q*8;
      uint32_t h0,l0,h1,l1,h2,l2,h3,l3;
      bfsplit2(src[0], src[1], h0, l0);
      bfsplit2(src[2], src[3], h1, l1);
      bfsplit2(src[4], src[5], h2, l2);
      bfsplit2(src[6], src[7], h3, l3);
      uint4 hv; hv.x=h0; hv.y=h1; hv.z=h2; hv.w=h3;
      uint4 lv; lv.x=l0; lv.y=l1; lv.z=l2; lv.w=l3;
      *(uint4*)&c_sh[n*CLD2 + sub*128 + q*8] = hv;
      *(uint4*)&c_sl[n*CLD2 + sub*128 + q*8] = lv;
    }
    __syncthreads();   // c_ts (u_sh) consumed before next sub restages u
  }

  // prefetch phase-2 (ch=0, it2=0) u tile
  #pragma unroll
  for (int it = 0; it < 8; ++it)
    pu[it] = *(const float4*)(ub_base + (size_t)urow[it]*DIN + uq[it]*4);

  // ---- phase 2: accum s^T over 256 i ----
  int mt = w & 3, nh = w >> 2;
  uint32_t atr_off = (((l & 7) + ((l >> 4) & 1)*8)*LDH + mt*16 + ((l >> 3) & 1)*8)*2;
  uint32_t atr_h = smem_u32(u_sh) + atr_off, atr_l = smem_u32(u_sl) + atr_off;
  uint32_t bco = ((nh*16 + ((l >> 4) & 1)*8 + (l & 7))*CLD2 + ((l >> 3) & 1)*8)*2;
  uint32_t bc_h = smem_u32(c_sh) + bco, bc_l = smem_u32(c_sl) + bco;
  float* sp = g_spart4 + ((size_t)(ic*BATCH + b)*NC)*DIN;

  for (int ch = 0; ch < 8; ++ch){
    float sacc[8];
    #pragma unroll
    for (int i = 0; i < 8; ++i) sacc[i] = 0.f;
    #pragma unroll
    for (int it2 = 0; it2 < 2; ++it2){
      __syncthreads();   // previous mma done / c convert done (first round)
      #pragma unroll
      for (int it = 0; it < 8; ++it){
        uint32_t h0, l0, h1, l1;
        bfsplit2(pu[it].x, pu[it].y, h0, l0);
        bfsplit2(pu[it].z, pu[it].w, h1, l1);
        *(uint2*)&u_sh[urow[it]*LDH + uq[it]*4] = make_uint2(h0, h1);
        *(uint2*)&u_sl[urow[it]*LDH + uq[it]*4] = make_uint2(l0, l1);
      }
      // prefetch next staging round
      if (!(ch == 7 && it2 == 1)){
        int nit2 = it2 ^ 1;
        int nch  = (it2 == 1) ? ch + 1 : ch;
        const float* np = ub_base + (size_t)nit2*128*DIN + nch*64;
        #pragma unroll
        for (int it = 0; it < 8; ++it)
          pu[it] = *(const float4*)(np + (size_t)urow[it]*DIN + uq[it]*4);
      }
      __syncthreads();
      #pragma unroll
      for (int is = 0; is < 8; ++is){
        uint32_t ah[4], al[4], bh[4], bl[4];
        ldmx4t(ah, atr_h + is*16*LDH*2);
        ldmx4t(al, atr_l + is*16*LDH*2);
        ldmx4(bh, bc_h + (it2*8 + is)*32);
        ldmx4(bl, bc_l + (it2*8 + is)*32);
        #pragma unroll
        for (int nt = 0; nt < 2; ++nt){
          mma16816(sacc + nt*4, ah, bh + nt*2);
          mma16816(sacc + nt*4, ah, bl + nt*2);
          mma16816(sacc + nt*4, al, bh + nt*2);
        }
      }
    }
    int kg = ch*64 + mt*16 + (l >> 2);
    #pragma unroll
    for (int nt = 0; nt < 2; ++nt){
      int n = nh*16 + nt*8 + 2*(l & 3);
      sp[(size_t)n*DIN + kg]       = sacc[nt*4];
      sp[(size_t)(n+1)*DIN + kg]   = sacc[nt*4+1];
      sp[(size_t)n*DIN + kg+8]     = sacc[nt*4+2];
      sp[(size_t)(n+1)*DIN + kg+8] = sacc[nt*4+3];
    }
  }
}

// ---------------- outv: out = squash(W^T s); v = W out ----------------
#define OUTV_SMEM ((DIN*WPAD + BG*DIN + BG*DC + BG*2)*4)

__global__ void __launch_bounds__(512,1) outv_kernel(
    const float* __restrict__ W, int mode, int doV, float* __restrict__ outF){
  extern __shared__ __align__(16) float sm[];
  float* W_s  = sm;
  float* s_s  = W_s + DIN*WPAD;
  float* o_s  = s_s + BG*DIN;
  float* sq_s = o_s + BG*DC;
  int n = blockIdx.x, bg = blockIdx.y, t = threadIdx.x;

  for (int m = t; m < DIN*DC/4; m += 512){
    int k = m >> 4, q = m & 15;
    *(float4*)&W_s[k*WPAD + q*4] = *(const float4*)(W + (size_t)k*ZDIM + n*DC + q*4);
  }
  for (int m = t; m < BG*DIN/4; m += 512){
    int b = m >> 7, f = (m & 127)*4;
    int gb = bg*BG + b;
    float4 r;
    if (mode == 0){
      float4 a0 = *(const float4*)&g_cspart[(0*BATCH+gb)*DIN + f];
      float4 a1 = *(const float4*)&g_cspart[(1*BATCH+gb)*DIN + f];
      float4 a2 = *(const float4*)&g_cspart[(2*BATCH+gb)*DIN + f];
      float4 a3 = *(const float4*)&g_cspart[(3*BATCH+gb)*DIN + f];
      r.x = a0.x+a1.x+a2.x+a3.x; r.y = a0.y+a1.y+a2.y+a3.y;
      r.z = a0.z+a1.z+a2.z+a3.z; r.w = a0.w+a1.w+a2.w+a3.w;
    } else {
      r.x = r.y = r.z = r.w = 0.f;
      #pragma unroll
      for (int p = 0; p < 4; ++p){
        float4 a = *(const float4*)&g_spart4[((size_t)(p*BATCH+gb)*NC + n)*DIN + f];
        r.x += a.x; r.y += a.y; r.z += a.z; r.w += a.w;
      }
    }
    *(float4*)&s_s[b*DIN + f] = r;
  }
  __syncthreads();

  int d = t & 63, bq = t >> 6, lane = t & 31;
  float accA[2] = {0.f, 0.f}, accB[2] = {0.f, 0.f};
  for (int kb = 0; kb < DIN; kb += 8){
    float w0 = W_s[(kb+0)*WPAD + d], w1 = W_s[(kb+1)*WPAD + d];
    float w2 = W_s[(kb+2)*WPAD + d], w3 = W_s[(kb+3)*WPAD + d];
    float w4 = W_s[(kb+4)*WPAD + d], w5 = W_s[(kb+5)*WPAD + d];
    float w6 = W_s[(kb+6)*WPAD + d], w7 = W_s[(kb+7)*WPAD + d];
    #pragma unroll
    for (int j = 0; j < 2; ++j){
      float4 sa = *(const float4*)&s_s[(bq*2+j)*DIN + kb];
      float4 sbv = *(const float4*)&s_s[(bq*2+j)*DIN + kb + 4];
      accA[j] += w0*sa.x + w1*sa.y + w2*sa.z + w3*sa.w;
      accB[j] += w4*sbv.x + w5*sbv.y + w6*sbv.z + w7*sbv.w;
    }
  }
  float acc[2] = {accA[0] + accB[0], accA[1] + accB[1]};
  int half = d >> 5;
  #pragma unroll
  for (int j = 0; j < 2; ++j){
    float sq = acc[j]*acc[j];
    #pragma unroll
    for (int o = 16; o; o >>= 1) sq += __shfl_xor_sync(0xffffffffu, sq, o);
    if (lane == 0) sq_s[(bq*2+j)*2 + half] = sq;
  }
  __syncthreads();
  #pragma unroll
  for (int j = 0; j < 2; ++j){
    int b = bq*2 + j;
    float inv = rsqrtf(sq_s[b*2] + sq_s[b*2+1] + EPSQ);
    float o = acc[j]*inv;
    o_s[b*DC + d] = o;
    if (outF) outF[((size_t)(bg*BG+b)*NC + n)*DC + d] = o;
  }
  if (!doV) return;
  __syncthreads();

  {
    int k = t;
    u64 wr[32];
    #pragma unroll
    for (int q = 0; q < 16; ++q){
      ulonglong2 wv = *(const ulonglong2*)&W_s[k*WPAD + q*4];
      wr[q*2] = wv.x; wr[q*2+1] = wv.y;
    }
    #pragma unroll 2
    for (int b = 0; b < BG; ++b){
      u64 a0 = 0ull, a1 = 0ull;
      const ulonglong2* ob = (const ulonglong2*)&o_s[b*DC];
      #pragma unroll
      for (int q = 0; q < 16; ++q){
        ulonglong2 ov = ob[q];
        a0 = fma2(wr[q*2], ov.x, a0);
        a1 = fma2(wr[q*2+1], ov.y, a1);
      }
      g_v[((size_t)(bg*BG+b)*NC + n)*DIN + k] = hadd2(add2(a0, a1));
    }
  }
}

// --------------------------------------------------------------------------
extern "C" void kernel_launch(void* const* d_in, const int* in_sizes, int n_in,
                              void* d_out, int out_size){
  const float* u = (const float*)d_in[0];
  const float* W = (const float*)d_in[1];
  float* out = (float*)d_out;
  (void)in_sizes; (void)n_in; (void)out_size;

  cudaFuncSetAttribute(outv_kernel,
                       cudaFuncAttributeMaxDynamicSharedMemorySize, OUTV_SMEM);
  cudaFuncSetAttribute(fused_routing,
                       cudaFuncAttributeMaxDynamicSharedMemorySize, FUSED_SMEM);

  colsum_kernel<<<dim3(BATCH, 4), 512>>>(u);
  outv_kernel<<<dim3(NC, NBG), 512, OUTV_SMEM>>>(W, 0, 1, nullptr);

  fused_routing<<<dim3(BATCH, 4), 256, FUSED_SMEM>>>(u);
  outv_kernel<<<dim3(NC, NBG), 512, OUTV_SMEM>>>(W, 1, 1, nullptr);

  fused_routing<<<dim3(BATCH, 4), 256, FUSED_SMEM>>>(u);
  outv_kernel<<<dim3(NC, NBG), 512, OUTV_SMEM>>>(W, 1, 0, out);
}

// round 15
// speedup vs baseline: 1.0363x; 1.0115x over previous
#include <cuda_runtime.h>
#include <cstdint>

#define BATCH 64
#define NIN   1024
#define DIN   512
#define NC    32
#define DC    64
#define ZDIM  2048
#define EPSQ  1e-7f
#define BG    16
#define NBG   (BATCH/BG)   // 4
#define WPAD  68
#define LDH   72     // staged u row: 64 halves + pad
#define CLD2  264    // staged c row: 256 halves + pad
#define CPD   132    // fp32 transpose-buffer pad

// smem byte offsets for fused kernel (single-buffered u/v, 256-i c)
#define USH 0
#define USL 18432
#define VSH 36864
#define VSL 41472
#define CSH 46080
#define CSL 62976
#define FUSED_SMEM 79872

typedef unsigned long long u64;
typedef unsigned short bfu;

__device__ __align__(16) float g_cspart[4*BATCH*DIN];               // 512 KB
__device__ __align__(16) float g_spart4[(size_t)4*BATCH*NC*DIN];    // 16 MB
__device__ __align__(16) float g_v[BATCH*NC*DIN];                   // 4 MB

// ---------------- helpers ----------------
__device__ __forceinline__ u64 fma2(u64 a, u64 b, u64 c){
  u64 d; asm("fma.rn.f32x2 %0, %1, %2, %3;" : "=l"(d) : "l"(a), "l"(b), "l"(c));
  return d;
}
__device__ __forceinline__ u64 add2(u64 a, u64 b){
  u64 d; asm("add.rn.f32x2 %0, %1, %2;" : "=l"(d) : "l"(a), "l"(b));
  return d;
}
__device__ __forceinline__ float hadd2(u64 v){
  float lo, hi; asm("mov.b64 {%0, %1}, %2;" : "=f"(lo), "=f"(hi) : "l"(v));
  return lo + hi;
}
__device__ __forceinline__ uint32_t smem_u32(const void* p){
  return (uint32_t)__cvta_generic_to_shared(p);
}
__device__ __forceinline__ void bfsplit2(float x0, float x1,
                                         uint32_t& hi, uint32_t& lo){
  asm("cvt.rn.bf16x2.f32 %0, %1, %2;" : "=r"(hi) : "f"(x1), "f"(x0));
  float h0 = __uint_as_float(hi << 16);
  float h1 = __uint_as_float(hi & 0xffff0000u);
  asm("cvt.rn.bf16x2.f32 %0, %1, %2;" : "=r"(lo) : "f"(x1 - h1), "f"(x0 - h0));
}
__device__ __forceinline__ void ldmx4(uint32_t* r, uint32_t addr){
  asm volatile("ldmatrix.sync.aligned.m8n8.x4.shared.b16 {%0,%1,%2,%3}, [%4];"
    : "=r"(r[0]), "=r"(r[1]), "=r"(r[2]), "=r"(r[3]) : "r"(addr));
}
__device__ __forceinline__ void ldmx4t(uint32_t* r, uint32_t addr){
  asm volatile("ldmatrix.sync.aligned.m8n8.x4.trans.shared.b16 {%0,%1,%2,%3}, [%4];"
    : "=r"(r[0]), "=r"(r[1]), "=r"(r[2]), "=r"(r[3]) : "r"(addr));
}
__device__ __forceinline__ void mma16816(float* c, const uint32_t* a,
                                         const uint32_t* b){
  asm volatile("mma.sync.aligned.m16n8k16.row.col.f32.bf16.bf16.f32 "
    "{%0,%1,%2,%3}, {%4,%5,%6,%7}, {%8,%9}, {%0,%1,%2,%3};"
    : "+f"(c[0]), "+f"(c[1]), "+f"(c[2]), "+f"(c[3])
    : "r"(a[0]), "r"(a[1]), "r"(a[2]), "r"(a[3]), "r"(b[0]), "r"(b[1]));
}

// ---------------- colsum ----------------
__global__ void __launch_bounds__(512) colsum_kernel(const float* __restrict__ u){
  int b = blockIdx.x, part = blockIdx.y, k = threadIdx.x;
  const float* up = u + ((size_t)b*NIN + (size_t)part*256)*DIN + k;
  float s = 0.f;
  #pragma unroll 8
  for (int i = 0; i < 256; ++i) s += up[(size_t)i*DIN];
  g_cspart[(part*BATCH + b)*DIN + k] = s;
}

// ---------------- fused routing: 256-i tiles; logits+softmax x2 + accum ----
__global__ void __launch_bounds__(256,2) fused_routing(const float* __restrict__ u){
  extern __shared__ __align__(16) char smem[];
  bfu* u_sh = (bfu*)(smem + USH);
  bfu* u_sl = (bfu*)(smem + USL);
  bfu* v_sh = (bfu*)(smem + VSH);
  bfu* v_sl = (bfu*)(smem + VSL);
  bfu* c_sh = (bfu*)(smem + CSH);
  bfu* c_sl = (bfu*)(smem + CSL);
  int b = blockIdx.x, ic = blockIdx.y;           // ic in 0..3 (256 i each)
  int t = threadIdx.x, w = t >> 5, l = t & 31;
  const float* ub_base = u + ((size_t)b*NIN + (size_t)ic*256)*DIN;
  const float* vg = g_v + (size_t)b*NC*DIN;

  int urow[8], uq[8];
  #pragma unroll
  for (int it = 0; it < 8; ++it){
    int idx = it*256 + t; urow[it] = idx >> 4; uq[it] = idx & 15;
  }
  int vn0 = t >> 4, vq0 = t & 15;
  int vn1 = (256 + t) >> 4, vq1 = t & 15;

  uint32_t aoff = ((w*16 + (l & 15))*LDH + (l >> 4)*8)*2;
  uint32_t a_hi = smem_u32(u_sh) + aoff, a_lo = smem_u32(u_sl) + aoff;
  uint32_t boff0 = (((l >> 4)*8 + (l & 7))*LDH + ((l >> 3) & 1)*8)*2;
  uint32_t boff1 = boff0 + 16*LDH*2;
  uint32_t bh0 = smem_u32(v_sh) + boff0, bh1 = smem_u32(v_sh) + boff1;
  uint32_t bl0 = smem_u32(v_sl) + boff0, bl1 = smem_u32(v_sl) + boff1;

  float4 pu[8], pv0, pv1;

  // ---- phase 1: logits + softmax + c-convert, two 128-i subtiles ----
  for (int sub = 0; sub < 2; ++sub){
    const float* ug = ub_base + (size_t)sub*128*DIN;
    float acc[16];
    #pragma unroll
    for (int i = 0; i < 16; ++i) acc[i] = 0.f;

    #pragma unroll
    for (int it = 0; it < 8; ++it)
      pu[it] = *(const float4*)(ug + (size_t)urow[it]*DIN + uq[it]*4);
    pv0 = *(const float4*)(vg + (size_t)vn0*DIN + vq0*4);
    pv1 = *(const float4*)(vg + (size_t)vn1*DIN + vq1*4);

    for (int kc = 0; kc < 8; ++kc){
      #pragma unroll
      for (int it = 0; it < 8; ++it){
        uint32_t h0, l0, h1, l1;
        bfsplit2(pu[it].x, pu[it].y, h0, l0);
        bfsplit2(pu[it].z, pu[it].w, h1, l1);
        *(uint2*)&u_sh[urow[it]*LDH + uq[it]*4] = make_uint2(h0, h1);
        *(uint2*)&u_sl[urow[it]*LDH + uq[it]*4] = make_uint2(l0, l1);
      }
      {
        uint32_t h0, l0, h1, l1;
        bfsplit2(pv0.x, pv0.y, h0, l0); bfsplit2(pv0.z, pv0.w, h1, l1);
        *(uint2*)&v_sh[vn0*LDH + vq0*4] = make_uint2(h0, h1);
        *(uint2*)&v_sl[vn0*LDH + vq0*4] = make_uint2(l0, l1);
        bfsplit2(pv1.x, pv1.y, h0, l0); bfsplit2(pv1.z, pv1.w, h1, l1);
        *(uint2*)&v_sh[vn1*LDH + vq1*4] = make_uint2(h0, h1);
        *(uint2*)&v_sl[vn1*LDH + vq1*4] = make_uint2(l0, l1);
      }
      if (kc < 7){
        int ko = (kc+1)*64;
        #pragma unroll
        for (int it = 0; it < 8; ++it)
          pu[it] = *(const float4*)(ug + (size_t)urow[it]*DIN + ko + uq[it]*4);
        pv0 = *(const float4*)(vg + (size_t)vn0*DIN + ko + vq0*4);
        pv1 = *(const float4*)(vg + (size_t)vn1*DIN + ko + vq1*4);
      }
      __syncthreads();
      #pragma unroll
      for (int ks = 0; ks < 4; ++ks){
        uint32_t kb = ks*32;
        uint32_t ah[4], al[4], bh[8], bl[8];
        ldmx4(ah, a_hi + kb); ldmx4(al, a_lo + kb);
        ldmx4(bh,   bh0 + kb); ldmx4(bh+4, bh1 + kb);
        ldmx4(bl,   bl0 + kb); ldmx4(bl+4, bl1 + kb);
        #pragma unroll
        for (int nt = 0; nt < 4; ++nt){
          mma16816(acc + nt*4, ah, bh + nt*2);
          mma16816(acc + nt*4, ah, bl + nt*2);
          mma16816(acc + nt*4, al, bh + nt*2);
        }
      }
      __syncthreads();
    }

    // softmax over n, stash c^T fp32 into u_sh alias
    float m0 = -1e30f, m1 = -1e30f;
    #pragma unroll
    for (int nt = 0; nt < 4; ++nt){
      m0 = fmaxf(m0, fmaxf(acc[nt*4], acc[nt*4+1]));
      m1 = fmaxf(m1, fmaxf(acc[nt*4+2], acc[nt*4+3]));
    }
    m0 = fmaxf(m0, __shfl_xor_sync(0xffffffffu, m0, 1));
    m0 = fmaxf(m0, __shfl_xor_sync(0xffffffffu, m0, 2));
    m1 = fmaxf(m1, __shfl_xor_sync(0xffffffffu, m1, 1));
    m1 = fmaxf(m1, __shfl_xor_sync(0xffffffffu, m1, 2));
    float s0 = 0.f, s1 = 0.f;
    #pragma unroll
    for (int nt = 0; nt < 4; ++nt){
      acc[nt*4]   = __expf(acc[nt*4]   - m0); s0 += acc[nt*4];
      acc[nt*4+1] = __expf(acc[nt*4+1] - m0); s0 += acc[nt*4+1];
      acc[nt*4+2] = __expf(acc[nt*4+2] - m1); s1 += acc[nt*4+2];
      acc[nt*4+3] = __expf(acc[nt*4+3] - m1); s1 += acc[nt*4+3];
    }
    s0 += __shfl_xor_sync(0xffffffffu, s0, 1);
    s0 += __shfl_xor_sync(0xffffffffu, s0, 2);
    s1 += __shfl_xor_sync(0xffffffffu, s1, 1);
    s1 += __shfl_xor_sync(0xffffffffu, s1, 2);
    float inv0 = 1.0f/s0, inv1 = 1.0f/s1;

    float* c_ts = (float*)u_sh;   // alias
    int i0 = w*16 + (l >> 2), i1 = i0 + 8;
    #pragma unroll
    for (int nt = 0; nt < 4; ++nt){
      int n = nt*8 + (l & 3)*2;
      c_ts[n*CPD + i0]     = acc[nt*4]*inv0;
      c_ts[(n+1)*CPD + i0] = acc[nt*4+1]*inv0;
      c_ts[n*CPD + i1]     = acc[nt*4+2]*inv1;
      c_ts[(n+1)*CPD + i1] = acc[nt*4+3]*inv1;
    }
    __syncthreads();
    // convert c subtile to bf16 hi/lo at column offset sub*128
    #pragma unroll
    for (int r = 0; r < 2; ++r){
      int idx = r*256 + t, n = idx >> 4, q = idx & 15;
      const float* src = c_ts + n*CPD + q*8;
      uint32_t h0,l0,h1,l1,h2,l2,h3,l3;
      bfsplit2(src[0], src[1], h0, l0);
      bfsplit2(src[2], src[3], h1, l1);
      bfsplit2(src[4], src[5], h2, l2);
      bfsplit2(src[6], src[7], h3, l3);
      uint4 hv; hv.x=h0; hv.y=h1; hv.z=h2; hv.w=h3;
      uint4 lv; lv.x=l0; lv.y=l1; lv.z=l2; lv.w=l3;
      *(uint4*)&c_sh[n*CLD2 + sub*128 + q*8] = hv;
      *(uint4*)&c_sl[n*CLD2 + sub*128 + q*8] = lv;
    }
    __syncthreads();   // c_ts (u_sh) consumed before next sub restages u
  }

  // prefetch phase-2 first tile in REVERSE order: (sub=1, ch=7)
  #pragma unroll
  for (int it = 0; it < 8; ++it)
    pu[it] = *(const float4*)(ub_base + (size_t)(128 + urow[it])*DIN + 7*64 + uq[it]*4);

  // ---- phase 2: accum s^T over 256 i, reverse traversal for L2 reuse ----
  int mt = w & 3, nh = w >> 2;
  uint32_t atr_off = (((l & 7) + ((l >> 4) & 1)*8)*LDH + mt*16 + ((l >> 3) & 1)*8)*2;
  uint32_t atr_h = smem_u32(u_sh) + atr_off, atr_l = smem_u32(u_sl) + atr_off;
  uint32_t bco = ((nh*16 + ((l >> 4) & 1)*8 + (l & 7))*CLD2 + ((l >> 3) & 1)*8)*2;
  uint32_t bc_h = smem_u32(c_sh) + bco, bc_l = smem_u32(c_sl) + bco;
  float* sp = g_spart4 + ((size_t)(ic*BATCH + b)*NC)*DIN;

  for (int ch = 7; ch >= 0; --ch){
    float sacc[8];
    #pragma unroll
    for (int i = 0; i < 8; ++i) sacc[i] = 0.f;
    #pragma unroll
    for (int s2 = 0; s2 < 2; ++s2){
      int it2 = 1 - s2;      // sub 1 first, then sub 0
      __syncthreads();   // previous mma done / c convert done (first round)
      #pragma unroll
      for (int it = 0; it < 8; ++it){
        uint32_t h0, l0, h1, l1;
        bfsplit2(pu[it].x, pu[it].y, h0, l0);
        bfsplit2(pu[it].z, pu[it].w, h1, l1);
        *(uint2*)&u_sh[urow[it]*LDH + uq[it]*4] = make_uint2(h0, h1);
        *(uint2*)&u_sl[urow[it]*LDH + uq[it]*4] = make_uint2(l0, l1);
      }
      // prefetch next staging round (reverse order)
      if (!(ch == 0 && it2 == 0)){
        int nit2 = it2 ^ 1;
        int nch  = (it2 == 0) ? ch - 1 : ch;
        const float* np = ub_base + (size_t)nit2*128*DIN + nch*64;
        #pragma unroll
        for (int it = 0; it < 8; ++it)
          pu[it] = *(const float4*)(np + (size_t)urow[it]*DIN + uq[it]*4);
      }
      __syncthreads();
      #pragma unroll
      for (int is = 0; is < 8; ++is){
        uint32_t ah[4], al[4], bh[4], bl[4];
        ldmx4t(ah, atr_h + is*16*LDH*2);
        ldmx4t(al, atr_l + is*16*LDH*2);
        ldmx4(bh, bc_h + (it2*8 + is)*32);
        ldmx4(bl, bc_l + (it2*8 + is)*32);
        #pragma unroll
        for (int nt = 0; nt < 2; ++nt){
          mma16816(sacc + nt*4, ah, bh + nt*2);
          mma16816(sacc + nt*4, ah, bl + nt*2);
          mma16816(sacc + nt*4, al, bh + nt*2);
        }
      }
    }
    int kg = ch*64 + mt*16 + (l >> 2);
    #pragma unroll
    for (int nt = 0; nt < 2; ++nt){
      int n = nh*16 + nt*8 + 2*(l & 3);
      sp[(size_t)n*DIN + kg]       = sacc[nt*4];
      sp[(size_t)(n+1)*DIN + kg]   = sacc[nt*4+1];
      sp[(size_t)n*DIN + kg+8]     = sacc[nt*4+2];
      sp[(size_t)(n+1)*DIN + kg+8] = sacc[nt*4+3];
    }
  }
}

// ---------------- outv: out = squash(W^T s); v = W out ----------------
#define OUTV_SMEM ((DIN*WPAD + BG*DIN + BG*DC + BG*2)*4)

__global__ void __launch_bounds__(512,1) outv_kernel(
    const float* __restrict__ W, int mode, int doV, float* __restrict__ outF){
  extern __shared__ __align__(16) float sm[];
  float* W_s  = sm;
  float* s_s  = W_s + DIN*WPAD;
  float* o_s  = s_s + BG*DIN;
  float* sq_s = o_s + BG*DC;
  int n = blockIdx.x, bg = blockIdx.y, t = threadIdx.x;

  for (int m = t; m < DIN*DC/4; m += 512){
    int k = m >> 4, q = m & 15;
    *(float4*)&W_s[k*WPAD + q*4] = *(const float4*)(W + (size_t)k*ZDIM + n*DC + q*4);
  }
  for (int m = t; m < BG*DIN/4; m += 512){
    int b = m >> 7, f = (m & 127)*4;
    int gb = bg*BG + b;
    float4 r;
    if (mode == 0){
      float4 a0 = *(const float4*)&g_cspart[(0*BATCH+gb)*DIN + f];
      float4 a1 = *(const float4*)&g_cspart[(1*BATCH+gb)*DIN + f];
      float4 a2 = *(const float4*)&g_cspart[(2*BATCH+gb)*DIN + f];
      float4 a3 = *(const float4*)&g_cspart[(3*BATCH+gb)*DIN + f];
      r.x = a0.x+a1.x+a2.x+a3.x; r.y = a0.y+a1.y+a2.y+a3.y;
      r.z = a0.z+a1.z+a2.z+a3.z; r.w = a0.w+a1.w+a2.w+a3.w;
    } else {
      r.x = r.y = r.z = r.w = 0.f;
      #pragma unroll
      for (int p = 0; p < 4; ++p){
        float4 a = *(const float4*)&g_spart4[((size_t)(p*BATCH+gb)*NC + n)*DIN + f];
        r.x += a.x; r.y += a.y; r.z += a.z; r.w += a.w;
      }
    }
    *(float4*)&s_s[b*DIN + f] = r;
  }
  __syncthreads();

  int d = t & 63, bq = t >> 6, lane = t & 31;
  float accA[2] = {0.f, 0.f}, accB[2] = {0.f, 0.f};
  for (int kb = 0; kb < DIN; kb += 8){
    float w0 = W_s[(kb+0)*WPAD + d], w1 = W_s[(kb+1)*WPAD + d];
    float w2 = W_s[(kb+2)*WPAD + d], w3 = W_s[(kb+3)*WPAD + d];
    float w4 = W_s[(kb+4)*WPAD + d], w5 = W_s[(kb+5)*WPAD + d];
    float w6 = W_s[(kb+6)*WPAD + d], w7 = W_s[(kb+7)*WPAD + d];
    #pragma unroll
    for (int j = 0; j < 2; ++j){
      float4 sa = *(const float4*)&s_s[(bq*2+j)*DIN + kb];
      float4 sbv = *(const float4*)&s_s[(bq*2+j)*DIN + kb + 4];
      accA[j] += w0*sa.x + w1*sa.y + w2*sa.z + w3*sa.w;
      accB[j] += w4*sbv.x + w5*sbv.y + w6*sbv.z + w7*sbv.w;
    }
  }
  float acc[2] = {accA[0] + accB[0], accA[1] + accB[1]};
  int half = d >> 5;
  #pragma unroll
  for (int j = 0; j < 2; ++j){
    float sq = acc[j]*acc[j];
    #pragma unroll
    for (int o = 16; o; o >>= 1) sq += __shfl_xor_sync(0xffffffffu, sq, o);
    if (lane == 0) sq_s[(bq*2+j)*2 + half] = sq;
  }
  __syncthreads();
  #pragma unroll
  for (int j = 0; j < 2; ++j){
    int b = bq*2 + j;
    float inv = rsqrtf(sq_s[b*2] + sq_s[b*2+1] + EPSQ);
    float o = acc[j]*inv;
    o_s[b*DC + d] = o;
    if (outF) outF[((size_t)(bg*BG+b)*NC + n)*DC + d] = o;
  }
  if (!doV) return;
  __syncthreads();

  {
    int k = t;
    u64 wr[32];
    #pragma unroll
    for (int q = 0; q < 16; ++q){
      ulonglong2 wv = *(const ulonglong2*)&W_s[k*WPAD + q*4];
      wr[q*2] = wv.x; wr[q*2+1] = wv.y;
    }
    #pragma unroll 2
    for (int b = 0; b < BG; ++b){
      u64 a0 = 0ull, a1 = 0ull;
      const ulonglong2* ob = (const ulonglong2*)&o_s[b*DC];
      #pragma unroll
      for (int q = 0; q < 16; ++q){
        ulonglong2 ov = ob[q];
        a0 = fma2(wr[q*2], ov.x, a0);
        a1 = fma2(wr[q*2+1], ov.y, a1);
      }
      g_v[((size_t)(bg*BG+b)*NC + n)*DIN + k] = hadd2(add2(a0, a1));
    }
  }
}

// --------------------------------------------------------------------------
extern "C" void kernel_launch(void* const* d_in, const int* in_sizes, int n_in,
                              void* d_out, int out_size){
  const float* u = (const float*)d_in[0];
  const float* W = (const float*)d_in[1];
  float* out = (float*)d_out;
  (void)in_sizes; (void)n_in; (void)out_size;

  cudaFuncSetAttribute(outv_kernel,
                       cudaFuncAttributeMaxDynamicSharedMemorySize, OUTV_SMEM);
  cudaFuncSetAttribute(fused_routing,
                       cudaFuncAttributeMaxDynamicSharedMemorySize, FUSED_SMEM);

  colsum_kernel<<<dim3(BATCH, 4), 512>>>(u);
  outv_kernel<<<dim3(NC, NBG), 512, OUTV_SMEM>>>(W, 0, 1, nullptr);

  fused_routing<<<dim3(BATCH, 4), 256, FUSED_SMEM>>>(u);
  outv_kernel<<<dim3(NC, NBG), 512, OUTV_SMEM>>>(W, 1, 1, nullptr);

  fused_routing<<<dim3(BATCH, 4), 256, FUSED_SMEM>>>(u);
  outv_kernel<<<dim3(NC, NBG), 512, OUTV_SMEM>>>(W, 1, 0, out);
}

// round 16
// speedup vs baseline: 1.0429x; 1.0064x over previous
#include <cuda_runtime.h>
#include <cstdint>

#define BATCH 64
#define NIN   1024
#define DIN   512
#define NC    32
#define DC    64
#define ZDIM  2048
#define EPSQ  1e-7f
#define BG    16
#define NBG   (BATCH/BG)   // 4
#define WPAD  68
#define LDH   72     // staged u row: 64 halves + pad
#define CLD2  264    // staged c row: 256 halves + pad
#define CPD   132    // fp32 transpose-buffer pad

// smem byte offsets for fused kernel (single-buffered u/v, 256-i c)
#define USH 0
#define USL 18432
#define VSH 36864
#define VSL 41472
#define CSH 46080
#define CSL 62976
#define FUSED_SMEM 79872

typedef unsigned long long u64;
typedef unsigned short bfu;

__device__ __align__(16) float g_cspart[4*BATCH*DIN];               // 512 KB
__device__ __align__(16) float g_spart4[(size_t)4*BATCH*NC*DIN];    // 16 MB
__device__ __align__(16) float g_v[BATCH*NC*DIN];                   // 4 MB

// ---------------- helpers ----------------
__device__ __forceinline__ u64 fma2(u64 a, u64 b, u64 c){
  u64 d; asm("fma.rn.f32x2 %0, %1, %2, %3;" : "=l"(d) : "l"(a), "l"(b), "l"(c));
  return d;
}
__device__ __forceinline__ u64 add2(u64 a, u64 b){
  u64 d; asm("add.rn.f32x2 %0, %1, %2;" : "=l"(d) : "l"(a), "l"(b));
  return d;
}
__device__ __forceinline__ float hadd2(u64 v){
  float lo, hi; asm("mov.b64 {%0, %1}, %2;" : "=f"(lo), "=f"(hi) : "l"(v));
  return lo + hi;
}
__device__ __forceinline__ uint32_t smem_u32(const void* p){
  return (uint32_t)__cvta_generic_to_shared(p);
}
__device__ __forceinline__ void bfsplit2(float x0, float x1,
                                         uint32_t& hi, uint32_t& lo){
  asm("cvt.rn.bf16x2.f32 %0, %1, %2;" : "=r"(hi) : "f"(x1), "f"(x0));
  float h0 = __uint_as_float(hi << 16);
  float h1 = __uint_as_float(hi & 0xffff0000u);
  asm("cvt.rn.bf16x2.f32 %0, %1, %2;" : "=r"(lo) : "f"(x1 - h1), "f"(x0 - h0));
}
__device__ __forceinline__ void ldmx4(uint32_t* r, uint32_t addr){
  asm volatile("ldmatrix.sync.aligned.m8n8.x4.shared.b16 {%0,%1,%2,%3}, [%4];"
    : "=r"(r[0]), "=r"(r[1]), "=r"(r[2]), "=r"(r[3]) : "r"(addr));
}
__device__ __forceinline__ void ldmx4t(uint32_t* r, uint32_t addr){
  asm volatile("ldmatrix.sync.aligned.m8n8.x4.trans.shared.b16 {%0,%1,%2,%3}, [%4];"
    : "=r"(r[0]), "=r"(r[1]), "=r"(r[2]), "=r"(r[3]) : "r"(addr));
}
__device__ __forceinline__ void mma16816(float* c, const uint32_t* a,
                                         const uint32_t* b){
  asm volatile("mma.sync.aligned.m16n8k16.row.col.f32.bf16.bf16.f32 "
    "{%0,%1,%2,%3}, {%4,%5,%6,%7}, {%8,%9}, {%0,%1,%2,%3};"
    : "+f"(c[0]), "+f"(c[1]), "+f"(c[2]), "+f"(c[3])
    : "r"(a[0]), "r"(a[1]), "r"(a[2]), "r"(a[3]), "r"(b[0]), "r"(b[1]));
}

// ---------------- colsum ----------------
__global__ void __launch_bounds__(512) colsum_kernel(const float* __restrict__ u){
  int b = blockIdx.x, part = blockIdx.y, k = threadIdx.x;
  const float* up = u + ((size_t)b*NIN + (size_t)part*256)*DIN + k;
  float s = 0.f;
  #pragma unroll 8
  for (int i = 0; i < 256; ++i) s += up[(size_t)i*DIN];
  g_cspart[(part*BATCH + b)*DIN + k] = s;
}

// ---------------- fused routing: 256-i tiles; logits+softmax x2 + accum ----
__global__ void __launch_bounds__(256,2) fused_routing(const float* __restrict__ u){
  extern __shared__ __align__(16) char smem[];
  bfu* u_sh = (bfu*)(smem + USH);
  bfu* u_sl = (bfu*)(smem + USL);
  bfu* v_sh = (bfu*)(smem + VSH);
  bfu* v_sl = (bfu*)(smem + VSL);
  bfu* c_sh = (bfu*)(smem + CSH);
  bfu* c_sl = (bfu*)(smem + CSL);
  int b = blockIdx.x, ic = blockIdx.y;           // ic in 0..3 (256 i each)
  int t = threadIdx.x, w = t >> 5, l = t & 31;
  const float* ub_base = u + ((size_t)b*NIN + (size_t)ic*256)*DIN;
  const float* vg = g_v + (size_t)b*NC*DIN;

  int urow[8], uq[8];
  #pragma unroll
  for (int it = 0; it < 8; ++it){
    int idx = it*256 + t; urow[it] = idx >> 4; uq[it] = idx & 15;
  }
  int vn0 = t >> 4, vq0 = t & 15;
  int vn1 = (256 + t) >> 4, vq1 = t & 15;

  uint32_t aoff = ((w*16 + (l & 15))*LDH + (l >> 4)*8)*2;
  uint32_t a_hi = smem_u32(u_sh) + aoff, a_lo = smem_u32(u_sl) + aoff;
  uint32_t boff0 = (((l >> 4)*8 + (l & 7))*LDH + ((l >> 3) & 1)*8)*2;
  uint32_t boff1 = boff0 + 16*LDH*2;
  uint32_t bh0 = smem_u32(v_sh) + boff0, bh1 = smem_u32(v_sh) + boff1;
  uint32_t bl0 = smem_u32(v_sl) + boff0, bl1 = smem_u32(v_sl) + boff1;

  float4 pu[8], pv0, pv1;

  // ---- phase 1: logits + softmax + c-convert, two 128-i subtiles ----
  for (int sub = 0; sub < 2; ++sub){
    const float* ug = ub_base + (size_t)sub*128*DIN;
    float acc[16];
    #pragma unroll
    for (int i = 0; i < 16; ++i) acc[i] = 0.f;

    #pragma unroll
    for (int it = 0; it < 8; ++it)
      pu[it] = *(const float4*)(ug + (size_t)urow[it]*DIN + uq[it]*4);
    pv0 = *(const float4*)(vg + (size_t)vn0*DIN + vq0*4);
    pv1 = *(const float4*)(vg + (size_t)vn1*DIN + vq1*4);

    for (int kc = 0; kc < 8; ++kc){
      #pragma unroll
      for (int it = 0; it < 8; ++it){
        uint32_t h0, l0, h1, l1;
        bfsplit2(pu[it].x, pu[it].y, h0, l0);
        bfsplit2(pu[it].z, pu[it].w, h1, l1);
        *(uint2*)&u_sh[urow[it]*LDH + uq[it]*4] = make_uint2(h0, h1);
        *(uint2*)&u_sl[urow[it]*LDH + uq[it]*4] = make_uint2(l0, l1);
      }
      {
        uint32_t h0, l0, h1, l1;
        bfsplit2(pv0.x, pv0.y, h0, l0); bfsplit2(pv0.z, pv0.w, h1, l1);
        *(uint2*)&v_sh[vn0*LDH + vq0*4] = make_uint2(h0, h1);
        *(uint2*)&v_sl[vn0*LDH + vq0*4] = make_uint2(l0, l1);
        bfsplit2(pv1.x, pv1.y, h0, l0); bfsplit2(pv1.z, pv1.w, h1, l1);
        *(uint2*)&v_sh[vn1*LDH + vq1*4] = make_uint2(h0, h1);
        *(uint2*)&v_sl[vn1*LDH + vq1*4] = make_uint2(l0, l1);
      }
      if (kc < 7){
        int ko = (kc+1)*64;
        #pragma unroll
        for (int it = 0; it < 8; ++it)
          pu[it] = *(const float4*)(ug + (size_t)urow[it]*DIN + ko + uq[it]*4);
        pv0 = *(const float4*)(vg + (size_t)vn0*DIN + ko + vq0*4);
        pv1 = *(const float4*)(vg + (size_t)vn1*DIN + ko + vq1*4);
      }
      __syncthreads();
      #pragma unroll
      for (int ks = 0; ks < 4; ++ks){
        uint32_t kb = ks*32;
        uint32_t ah[4], al[4], bh[8], bl[8];
        ldmx4(ah, a_hi + kb); ldmx4(al, a_lo + kb);
        ldmx4(bh,   bh0 + kb); ldmx4(bh+4, bh1 + kb);
        ldmx4(bl,   bl0 + kb); ldmx4(bl+4, bl1 + kb);
        #pragma unroll
        for (int nt = 0; nt < 4; ++nt){
          mma16816(acc + nt*4, ah, bh + nt*2);
          mma16816(acc + nt*4, ah, bl + nt*2);
          mma16816(acc + nt*4, al, bh + nt*2);
        }
      }
      __syncthreads();
    }

    // softmax over n, stash c^T fp32 into u_sh alias
    float m0 = -1e30f, m1 = -1e30f;
    #pragma unroll
    for (int nt = 0; nt < 4; ++nt){
      m0 = fmaxf(m0, fmaxf(acc[nt*4], acc[nt*4+1]));
      m1 = fmaxf(m1, fmaxf(acc[nt*4+2], acc[nt*4+3]));
    }
    m0 = fmaxf(m0, __shfl_xor_sync(0xffffffffu, m0, 1));
    m0 = fmaxf(m0, __shfl_xor_sync(0xffffffffu, m0, 2));
    m1 = fmaxf(m1, __shfl_xor_sync(0xffffffffu, m1, 1));
    m1 = fmaxf(m1, __shfl_xor_sync(0xffffffffu, m1, 2));
    float s0 = 0.f, s1 = 0.f;
    #pragma unroll
    for (int nt = 0; nt < 4; ++nt){
      acc[nt*4]   = __expf(acc[nt*4]   - m0); s0 += acc[nt*4];
      acc[nt*4+1] = __expf(acc[nt*4+1] - m0); s0 += acc[nt*4+1];
      acc[nt*4+2] = __expf(acc[nt*4+2] - m1); s1 += acc[nt*4+2];
      acc[nt*4+3] = __expf(acc[nt*4+3] - m1); s1 += acc[nt*4+3];
    }
    s0 += __shfl_xor_sync(0xffffffffu, s0, 1);
    s0 += __shfl_xor_sync(0xffffffffu, s0, 2);
    s1 += __shfl_xor_sync(0xffffffffu, s1, 1);
    s1 += __shfl_xor_sync(0xffffffffu, s1, 2);
    float inv0 = 1.0f/s0, inv1 = 1.0f/s1;

    float* c_ts = (float*)u_sh;   // alias
    int i0 = w*16 + (l >> 2), i1 = i0 + 8;
    #pragma unroll
    for (int nt = 0; nt < 4; ++nt){
      int n = nt*8 + (l & 3)*2;
      c_ts[n*CPD + i0]     = acc[nt*4]*inv0;
      c_ts[(n+1)*CPD + i0] = acc[nt*4+1]*inv0;
      c_ts[n*CPD + i1]     = acc[nt*4+2]*inv1;
      c_ts[(n+1)*CPD + i1] = acc[nt*4+3]*inv1;
    }
    __syncthreads();
    // convert c subtile to bf16 hi/lo at column offset sub*128
    #pragma unroll
    for (int r = 0; r < 2; ++r){
      int idx = r*256 + t, n = idx >> 4, q = idx & 15;
      const float* src = c_ts + n*CPD + q*8;
      uint32_t h0,l0,h1,l1,h2,l2,h3,l3;
      bfsplit2(src[0], src[1], h0, l0);
      bfsplit2(src[2], src[3], h1, l1);
      bfsplit2(src[4], src[5], h2, l2);
      bfsplit2(src[6], src[7], h3, l3);
      uint4 hv; hv.x=h0; hv.y=h1; hv.z=h2; hv.w=h3;
      uint4 lv; lv.x=l0; lv.y=l1; lv.z=l2; lv.w=l3;
      *(uint4*)&c_sh[n*CLD2 + sub*128 + q*8] = hv;
      *(uint4*)&c_sl[n*CLD2 + sub*128 + q*8] = lv;
    }
    __syncthreads();   // c_ts (u_sh) consumed before next sub restages u
  }

  // prefetch phase-2 first tile in REVERSE order: (sub=1, ch=7)
  #pragma unroll
  for (int it = 0; it < 8; ++it)
    pu[it] = *(const float4*)(ub_base + (size_t)(128 + urow[it])*DIN + 7*64 + uq[it]*4);

  // ---- phase 2: accum s^T over 256 i, reverse traversal for L2 reuse ----
  int mt = w & 3, nh = w >> 2;
  uint32_t atr_off = (((l & 7) + ((l >> 4) & 1)*8)*LDH + mt*16 + ((l >> 3) & 1)*8)*2;
  uint32_t atr_h = smem_u32(u_sh) + atr_off, atr_l = smem_u32(u_sl) + atr_off;
  uint32_t bco = ((nh*16 + ((l >> 4) & 1)*8 + (l & 7))*CLD2 + ((l >> 3) & 1)*8)*2;
  uint32_t bc_h = smem_u32(c_sh) + bco, bc_l = smem_u32(c_sl) + bco;
  float* sp = g_spart4 + ((size_t)(ic*BATCH + b)*NC)*DIN;

  for (int ch = 7; ch >= 0; --ch){
    float sacc[8];
    #pragma unroll
    for (int i = 0; i < 8; ++i) sacc[i] = 0.f;
    #pragma unroll
    for (int s2 = 0; s2 < 2; ++s2){
      int it2 = 1 - s2;      // sub 1 first, then sub 0
      __syncthreads();   // previous mma done / c convert done (first round)
      #pragma unroll
      for (int it = 0; it < 8; ++it){
        uint32_t h0, l0, h1, l1;
        bfsplit2(pu[it].x, pu[it].y, h0, l0);
        bfsplit2(pu[it].z, pu[it].w, h1, l1);
        *(uint2*)&u_sh[urow[it]*LDH + uq[it]*4] = make_uint2(h0, h1);
        *(uint2*)&u_sl[urow[it]*LDH + uq[it]*4] = make_uint2(l0, l1);
      }
      // prefetch next staging round (reverse order)
      if (!(ch == 0 && it2 == 0)){
        int nit2 = it2 ^ 1;
        int nch  = (it2 == 0) ? ch - 1 : ch;
        const float* np = ub_base + (size_t)nit2*128*DIN + nch*64;
        #pragma unroll
        for (int it = 0; it < 8; ++it)
          pu[it] = *(const float4*)(np + (size_t)urow[it]*DIN + uq[it]*4);
      }
      __syncthreads();
      #pragma unroll
      for (int is = 0; is < 8; ++is){
        uint32_t ah[4], al[4], bh[4], bl[4];
        ldmx4t(ah, atr_h + is*16*LDH*2);
        ldmx4t(al, atr_l + is*16*LDH*2);
        ldmx4(bh, bc_h + (it2*8 + is)*32);
        ldmx4(bl, bc_l + (it2*8 + is)*32);
        #pragma unroll
        for (int nt = 0; nt < 2; ++nt){
          mma16816(sacc + nt*4, ah, bh + nt*2);
          mma16816(sacc + nt*4, ah, bl + nt*2);
          mma16816(sacc + nt*4, al, bh + nt*2);
        }
      }
    }
    int kg = ch*64 + mt*16 + (l >> 2);
    #pragma unroll
    for (int nt = 0; nt < 2; ++nt){
      int n = nh*16 + nt*8 + 2*(l & 3);
      sp[(size_t)n*DIN + kg]       = sacc[nt*4];
      sp[(size_t)(n+1)*DIN + kg]   = sacc[nt*4+1];
      sp[(size_t)n*DIN + kg+8]     = sacc[nt*4+2];
      sp[(size_t)(n+1)*DIN + kg+8] = sacc[nt*4+3];
    }
  }
}

// ---------------- outv: out = squash(W^T s); v = W out  (1024 threads) ----
#define OUTV_SMEM ((DIN*WPAD + BG*DIN + BG*DC + BG*2)*4)

__global__ void __launch_bounds__(1024,1) outv_kernel(
    const float* __restrict__ W, int mode, int doV, float* __restrict__ outF){
  extern __shared__ __align__(16) float sm[];
  float* W_s  = sm;
  float* s_s  = W_s + DIN*WPAD;
  float* o_s  = s_s + BG*DIN;
  float* sq_s = o_s + BG*DC;
  int n = blockIdx.x, bg = blockIdx.y, t = threadIdx.x;

  for (int m = t; m < DIN*DC/4; m += 1024){
    int k = m >> 4, q = m & 15;
    *(float4*)&W_s[k*WPAD + q*4] = *(const float4*)(W + (size_t)k*ZDIM + n*DC + q*4);
  }
  for (int m = t; m < BG*DIN/4; m += 1024){
    int b = m >> 7, f = (m & 127)*4;
    int gb = bg*BG + b;
    float4 r;
    if (mode == 0){
      float4 a0 = *(const float4*)&g_cspart[(0*BATCH+gb)*DIN + f];
      float4 a1 = *(const float4*)&g_cspart[(1*BATCH+gb)*DIN + f];
      float4 a2 = *(const float4*)&g_cspart[(2*BATCH+gb)*DIN + f];
      float4 a3 = *(const float4*)&g_cspart[(3*BATCH+gb)*DIN + f];
      r.x = a0.x+a1.x+a2.x+a3.x; r.y = a0.y+a1.y+a2.y+a3.y;
      r.z = a0.z+a1.z+a2.z+a3.z; r.w = a0.w+a1.w+a2.w+a3.w;
    } else {
      r.x = r.y = r.z = r.w = 0.f;
      #pragma unroll
      for (int p = 0; p < 4; ++p){
        float4 a = *(const float4*)&g_spart4[((size_t)(p*BATCH+gb)*NC + n)*DIN + f];
        r.x += a.x; r.y += a.y; r.z += a.z; r.w += a.w;
      }
    }
    *(float4*)&s_s[b*DIN + f] = r;
  }
  __syncthreads();

  // out phase: one (b, d) per thread; ILP split over k
  int d = t & 63, bq = t >> 6;           // bq 0..15
  int lane = t & 31, half = (t >> 5) & 1;
  float accA = 0.f, accB = 0.f;
  for (int kb = 0; kb < DIN; kb += 8){
    float w0 = W_s[(kb+0)*WPAD + d], w1 = W_s[(kb+1)*WPAD + d];
    float w2 = W_s[(kb+2)*WPAD + d], w3 = W_s[(kb+3)*WPAD + d];
    float w4 = W_s[(kb+4)*WPAD + d], w5 = W_s[(kb+5)*WPAD + d];
    float w6 = W_s[(kb+6)*WPAD + d], w7 = W_s[(kb+7)*WPAD + d];
    float4 sa  = *(const float4*)&s_s[bq*DIN + kb];
    float4 sbv = *(const float4*)&s_s[bq*DIN + kb + 4];
    accA += w0*sa.x + w1*sa.y + w2*sa.z + w3*sa.w;
    accB += w4*sbv.x + w5*sbv.y + w6*sbv.z + w7*sbv.w;
  }
  float acc = accA + accB;
  {
    float sq = acc*acc;
    #pragma unroll
    for (int o = 16; o; o >>= 1) sq += __shfl_xor_sync(0xffffffffu, sq, o);
    if (lane == 0) sq_s[bq*2 + half] = sq;
  }
  __syncthreads();
  {
    float inv = rsqrtf(sq_s[bq*2] + sq_s[bq*2+1] + EPSQ);
    float o = acc*inv;
    o_s[bq*DC + d] = o;
    if (outF) outF[((size_t)(bg*BG+bq)*NC + n)*DC + d] = o;
  }
  if (!doV) return;
  __syncthreads();

  // v phase: k = t&511, b-half = t>>9 (8 b each); d split in two halves
  {
    int kv = t & 511, bh = t >> 9;
    float pacc[8];
    #pragma unroll
    for (int i = 0; i < 8; ++i) pacc[i] = 0.f;
    #pragma unroll
    for (int dh = 0; dh < 2; ++dh){
      u64 wr[16];
      #pragma unroll
      for (int q = 0; q < 8; ++q){
        ulonglong2 wv = *(const ulonglong2*)&W_s[kv*WPAD + dh*32 + q*4];
        wr[q*2] = wv.x; wr[q*2+1] = wv.y;
      }
      #pragma unroll
      for (int b8 = 0; b8 < 8; ++b8){
        int b = bh*8 + b8;
        u64 a0 = 0ull, a1 = 0ull;
        const ulonglong2* ob = (const ulonglong2*)&o_s[b*DC + dh*32];
        #pragma unroll
        for (int q = 0; q < 8; ++q){
          ulonglong2 ov = ob[q];
          a0 = fma2(wr[q*2],   ov.x, a0);
          a1 = fma2(wr[q*2+1], ov.y, a1);
        }
        pacc[b8] += hadd2(add2(a0, a1));
      }
    }
    #pragma unroll
    for (int b8 = 0; b8 < 8; ++b8)
      g_v[((size_t)(bg*BG + bh*8 + b8)*NC + n)*DIN + kv] = pacc[b8];
  }
}

// --------------------------------------------------------------------------
extern "C" void kernel_launch(void* const* d_in, const int* in_sizes, int n_in,
                              void* d_out, int out_size){
  const float* u = (const float*)d_in[0];
  const float* W = (const float*)d_in[1];
  float* out = (float*)d_out;
  (void)in_sizes; (void)n_in; (void)out_size;

  cudaFuncSetAttribute(outv_kernel,
                       cudaFuncAttributeMaxDynamicSharedMemorySize, OUTV_SMEM);
  cudaFuncSetAttribute(fused_routing,
                       cudaFuncAttributeMaxDynamicSharedMemorySize, FUSED_SMEM);

  colsum_kernel<<<dim3(BATCH, 4), 512>>>(u);
  outv_kernel<<<dim3(NC, NBG), 1024, OUTV_SMEM>>>(W, 0, 1, nullptr);

  fused_routing<<<dim3(BATCH, 4), 256, FUSED_SMEM>>>(u);
  outv_kernel<<<dim3(NC, NBG), 1024, OUTV_SMEM>>>(W, 1, 1, nullptr);

  fused_routing<<<dim3(BATCH, 4), 256, FUSED_SMEM>>>(u);
  outv_kernel<<<dim3(NC, NBG), 1024, OUTV_SMEM>>>(W, 1, 0, out);
}